// round 11
// baseline (speedup 1.0000x reference)
#include <cuda_runtime.h>
#include <cuda_bf16.h>
#include <math.h>
#include <stdint.h>

// Problem dims (fixed)
#define BB   256      // batch
#define NI   16384    // n_items
#define DM   512      // d_model
#define DFF  2048     // ff dim
#define NNZV (NI*33)  // 540672 = 16384*33 exactly
#define NSP1 16       // K-splits for GEMM1
#define NCTA_MID 128  // CTAs in the fused middle kernel
#define NCTA_CSR 64   // CTAs in the fused CSR kernel

// ---------------- scratch (device globals; no allocation allowed) ----------
__device__ float g_x0T[NI*BB];               // x0 transposed [N,B] fp32
__device__ __nv_bfloat16 g_x0Th[NI*BB];      // x0 transposed [N,B] bf16
__device__ __nv_bfloat16 g_xth[NI*BB];       // x_t [N,B] bf16 (k-major for GEMM1)
__device__ __nv_bfloat16 g_Winh[DM*NI];      // W_in bf16
__device__ __nv_bfloat16 g_Wouth[NI*DM];     // W_out bf16
__device__ float g_part[NSP1*BB*DM];         // split-K partials (reused)
__device__ float g_h  [BB*DM];
__device__ float g_h1 [BB*DM];
__device__ float g_f1 [BB*DFF];
__device__ __nv_bfloat16 g_h2h[BB*DM];       // h2 bf16 (only loss GEMM reads it)
// folded attention weights
__device__ float g_WvT[DM*DM];               // Wv transposed [k][d]
__device__ float g_We [DM*DM];               // We = Wo @ Wv, [n][k] row-major
__device__ float g_bc [DM];                  // bc = Wo @ bv + bo
// CSR build scratch
__device__ int   g_cnt[NI];       // zero-initialized; csr kernel re-zeros each replay
__device__ int   g_off[NI + 1];
__device__ int   g_wp [NI];
__device__ int2  g_cpack[NNZV];   // packed (col, val_bits)
__device__ int   g_bsum[NCTA_CSR];
__device__ int   g_bexcl[NCTA_CSR];
// barrier counters (reset by last CTA each replay)
__device__ int   g_bar[8];        // middle kernel
__device__ int   g_cbar[8];       // csr kernel

// ---------------- helpers ----------------
__device__ __forceinline__ float tf32r(float x) {
    uint32_t r;
    asm("cvt.rna.tf32.f32 %0, %1;" : "=r"(r) : "f"(x));
    return __uint_as_float(r);
}

__device__ __forceinline__ uint32_t bf2u(__nv_bfloat162 h) {
    uint32_t u;
    memcpy(&u, &h, 4);
    return u;
}

#define MMA_TF32(c, a, b) \
    asm volatile("mma.sync.aligned.m16n8k8.row.col.f32.tf32.tf32.f32 " \
                 "{%0,%1,%2,%3}, {%4,%5,%6,%7}, {%8,%9}, {%0,%1,%2,%3};" \
                 : "+f"((c)[0]), "+f"((c)[1]), "+f"((c)[2]), "+f"((c)[3]) \
                 : "r"((a)[0]), "r"((a)[1]), "r"((a)[2]), "r"((a)[3]), \
                   "r"((b)[0]), "r"((b)[1]))

#define MMA_BF16(c, a, b) \
    asm volatile("mma.sync.aligned.m16n8k16.row.col.f32.bf16.bf16.f32 " \
                 "{%0,%1,%2,%3}, {%4,%5,%6,%7}, {%8,%9}, {%0,%1,%2,%3};" \
                 : "+f"((c)[0]), "+f"((c)[1]), "+f"((c)[2]), "+f"((c)[3]) \
                 : "r"((a)[0]), "r"((a)[1]), "r"((a)[2]), "r"((a)[3]), \
                   "r"((b)[0]), "r"((b)[1]))

#define LDMATRIX_X4_TRANS(r0, r1, r2, r3, addr) \
    asm volatile("ldmatrix.sync.aligned.m8n8.x4.trans.shared.b16 {%0,%1,%2,%3}, [%4];" \
                 : "=r"(r0), "=r"(r1), "=r"(r2), "=r"(r3) : "r"(addr))

__device__ __forceinline__ float gelu_exact(float s) {
    return 0.5f * s * (1.f + erff(s * 0.70710678118654752f));
}

// =================== fused CSR build (persistent, 64 CTAs) ==================
__device__ __forceinline__ void csrbar(int i) {
    __syncthreads();
    if (threadIdx.x == 0) {
        __threadfence();
        atomicAdd(&g_cbar[i], 1);
        while (atomicAdd(&g_cbar[i], 0) < NCTA_CSR) { }
    }
    __syncthreads();
}

__global__ __launch_bounds__(256) void csr_kernel(
    const int* __restrict__ rows, const int* __restrict__ cols,
    const float* __restrict__ vals, float* __restrict__ loss) {
    __shared__ int ws[8];
    int cta = blockIdx.x, tid = threadIdx.x;
    int gtid = cta * 256 + tid;          // 0..16383

    // --- phase A: histogram (NNZV = 16384*33, exact) ---
#pragma unroll 4
    for (int it = 0; it < 33; it++)
        atomicAdd(&g_cnt[rows[it * 16384 + gtid]], 1);
    csrbar(0);

    // --- phase B: per-CTA exclusive scan over its 256 bins; reset cnt ---
    {
        int c = g_cnt[gtid];
        g_cnt[gtid] = 0;
        int lane = tid & 31, w = tid >> 5;
        int inc = c;
#pragma unroll
        for (int o = 1; o < 32; o <<= 1) {
            int v = __shfl_up_sync(0xffffffffu, inc, o);
            if (lane >= o) inc += v;
        }
        if (lane == 31) ws[w] = inc;
        __syncthreads();
        if (tid < 8) {
            int v = ws[tid];
#pragma unroll
            for (int o = 1; o < 8; o <<= 1) {
                int u = __shfl_up_sync(0xffu, v, o);
                if (tid >= o) v += u;
            }
            ws[tid] = v;
        }
        __syncthreads();
        int base = (w > 0) ? ws[w - 1] : 0;
        g_off[gtid] = base + inc - c;
        if (tid == 255) g_bsum[cta] = ws[7];
        __syncthreads();
    }
    csrbar(1);

    // --- phase C: CTA 0 scans the 64 block sums; zero loss ---
    if (cta == 0) {
        int lane = tid & 31;
        int v = 0, inc = 0;
        if (tid < 64) {
            v = g_bsum[tid];
            inc = v;
#pragma unroll
            for (int o = 1; o < 32; o <<= 1) {
                int u = __shfl_up_sync(0xffffffffu, inc, o);
                if (lane >= o) inc += u;
            }
            if (lane == 31) ws[tid >> 5] = inc;
        }
        __syncthreads();
        if (tid < 64) {
            int base = (tid >= 32) ? ws[0] : 0;
            g_bexcl[tid] = base + inc - v;
        }
        if (tid == 0) {
            *loss = 0.f;
            g_off[NI] = 0;   // placeholder; real total below after sync
        }
        __syncthreads();
        if (tid == 0) g_off[NI] = ws[0] + ws[1];
    }
    csrbar(2);

    // --- phase D: apply block offsets; init write pointers ---
    {
        int val = g_off[gtid] + g_bexcl[cta];
        g_off[gtid] = val;
        g_wp[gtid] = val;
    }
    csrbar(3);

    // --- phase E: fill (counting-sort placement) ---
#pragma unroll 2
    for (int it = 0; it < 33; it++) {
        int i = it * 16384 + gtid;
        int r = rows[i];
        int p = atomicAdd(&g_wp[r], 1);
        g_cpack[p] = make_int2(cols[i], __float_as_int(vals[i]));
    }

    // --- ticket reset of barrier counters for next replay ---
    __syncthreads();
    if (tid == 0) {
        int old = atomicAdd(&g_cbar[7], 1);
        if (old == NCTA_CSR - 1) {
#pragma unroll
            for (int i = 0; i < 8; i++) atomicExch(&g_cbar[i], 0);
        }
    }
}

// ------- merged transpose (x0, Wv) + weight cvt + bc = Wo@bv + bo ----------
__global__ void transcvt_kernel(const float* __restrict__ x,
                                float* __restrict__ xt,
                                __nv_bfloat16* __restrict__ xh,
                                const float* __restrict__ wa, __nv_bfloat16* __restrict__ oa,
                                const float* __restrict__ wb, __nv_bfloat16* __restrict__ ob,
                                const float* __restrict__ Wv,
                                const float* __restrict__ Wo,
                                const float* __restrict__ bv,
                                const float* __restrict__ bo) {
    __shared__ float s[32][33];
    int blk = blockIdx.x, tid = threadIdx.x;
    if (blk < 4096) {
        // x0 [B,N] -> x0T [N,B] fp32 + bf16
        int n0 = (blk & 511) * 32, b0 = (blk >> 9) * 32;
        int tx = tid & 31, ty = tid >> 5;
#pragma unroll
        for (int i = 0; i < 32; i += 8)
            s[ty + i][tx] = x[(size_t)(b0 + ty + i) * NI + n0 + tx];
        __syncthreads();
#pragma unroll
        for (int i = 0; i < 32; i += 8) {
            float val = s[tx][ty + i];
            size_t idx = (size_t)(n0 + ty + i) * BB + b0 + tx;
            xt[idx] = val;
            xh[idx] = __float2bfloat16(val);
        }
    } else if (blk < 12288) {
        // W_in / W_out fp32 -> bf16
        int blk2 = blk - 4096;
        const float* src;
        __nv_bfloat16* dst;
        size_t base;
        if (blk2 < 4096) { src = wa; dst = oa; base = (size_t)blk2 * 2048; }
        else             { src = wb; dst = ob; base = (size_t)(blk2 - 4096) * 2048; }
        size_t i = base + tid * 8;
        float4 v0 = *(const float4*)(src + i);
        float4 v1 = *(const float4*)(src + i + 4);
        uint4 o;
        o.x = bf2u(__floats2bfloat162_rn(v0.x, v0.y));
        o.y = bf2u(__floats2bfloat162_rn(v0.z, v0.w));
        o.z = bf2u(__floats2bfloat162_rn(v1.x, v1.y));
        o.w = bf2u(__floats2bfloat162_rn(v1.z, v1.w));
        *(uint4*)(dst + i) = o;
    } else if (blk < 12544) {
        // Wv [d][k] -> WvT [k][d]  (32x32 tiles)
        int idx = blk - 12288;
        int k0 = (idx & 15) * 32, d0 = (idx >> 4) * 32;
        int tx = tid & 31, ty = tid >> 5;
#pragma unroll
        for (int i = 0; i < 32; i += 8)
            s[ty + i][tx] = Wv[(size_t)(d0 + ty + i) * DM + k0 + tx];
        __syncthreads();
#pragma unroll
        for (int i = 0; i < 32; i += 8)
            g_WvT[(size_t)(k0 + ty + i) * DM + d0 + tx] = s[tx][ty + i];
    } else {
        // bc[n] = sum_d Wo[n,d]*bv[d] + bo[n]   (warp per row)
        int w = tid >> 5, lane = tid & 31;
        for (int n = w; n < DM; n += 8) {
            float acc = 0.f;
            const float* wr = Wo + (size_t)n * DM;
            for (int d = lane; d < DM; d += 32) acc += wr[d] * bv[d];
#pragma unroll
            for (int o = 16; o > 0; o >>= 1) acc += __shfl_xor_sync(0xffffffffu, acc, o);
            if (lane == 0) g_bc[n] = acc + bo[n];
        }
    }
}

// ---------------- gather: xth[r,:] = bf16(x0T[r,:] - tc[:]*sum val*x0Th[col,:]) --
__global__ void gather_kernel(const float* __restrict__ x0T,
                              const __nv_bfloat16* __restrict__ x0Th,
                              const int* __restrict__ off,
                              const int2* __restrict__ cpack,
                              const float* __restrict__ t,
                              __nv_bfloat16* __restrict__ xth) {
    int r = blockIdx.x;
    int tid = threadIdx.x;        // 0..127
    int b2 = tid * 2;
    int s = off[r], e = off[r + 1];
    float acc0 = 0.f, acc1 = 0.f;
    int j = s;
    for (; j + 3 < e; j += 4) {
        int2 cv0 = __ldg(&cpack[j]),     cv1 = __ldg(&cpack[j + 1]);
        int2 cv2 = __ldg(&cpack[j + 2]), cv3 = __ldg(&cpack[j + 3]);
        float v0 = __int_as_float(cv0.y), v1 = __int_as_float(cv1.y);
        float v2 = __int_as_float(cv2.y), v3 = __int_as_float(cv3.y);
        float2 f0 = __bfloat1622float2(*(const __nv_bfloat162*)(x0Th + (size_t)cv0.x * BB + b2));
        float2 f1 = __bfloat1622float2(*(const __nv_bfloat162*)(x0Th + (size_t)cv1.x * BB + b2));
        float2 f2 = __bfloat1622float2(*(const __nv_bfloat162*)(x0Th + (size_t)cv2.x * BB + b2));
        float2 f3 = __bfloat1622float2(*(const __nv_bfloat162*)(x0Th + (size_t)cv3.x * BB + b2));
        acc0 += v0 * f0.x + v1 * f1.x + v2 * f2.x + v3 * f3.x;
        acc1 += v0 * f0.y + v1 * f1.y + v2 * f2.y + v3 * f3.y;
    }
    for (; j < e; j++) {
        int2 cv0 = __ldg(&cpack[j]);
        float v0 = __int_as_float(cv0.y);
        float2 f0 = __bfloat1622float2(*(const __nv_bfloat162*)(x0Th + (size_t)cv0.x * BB + b2));
        acc0 += v0 * f0.x;
        acc1 += v0 * f0.y;
    }
    float tc0 = 0.5f * t[b2];
    float tc1 = 0.5f * t[b2 + 1];
    float2 xv = *(const float2*)(x0T + (size_t)r * BB + b2);
    __nv_bfloat162 ov = __floats2bfloat162_rn(xv.x - tc0 * acc0, xv.y - tc1 * acc1);
    *(__nv_bfloat162*)(xth + (size_t)r * BB + b2) = ov;
}

// 64x64 TF32 tile GEMM with 256 threads (8 warps, 2m x 4n, warp 32x16).
// act: 0 = +bias, 1 = +bias+gelu, 2 = raw store (partials)
__device__ __noinline__ void tile_gemm64(const float* __restrict__ A,
                                         const float* __restrict__ W,
                                         const float* __restrict__ bias,
                                         float* __restrict__ out,
                                         int N2, int lda, int m0, int n0,
                                         int k0, int kend, int act,
                                         float As[64][20], float Ws[64][20]) {
    int tid = threadIdx.x;
    int w = tid >> 5, lane = tid & 31;
    int wm = (w >> 2) * 32, wn = (w & 3) * 16;
    int g = lane >> 2, tg = lane & 3;
    int mm = tid >> 2, kk = (tid & 3) * 4;

    float acc[2][2][4];
#pragma unroll
    for (int i = 0; i < 2; i++)
#pragma unroll
        for (int j = 0; j < 2; j++)
#pragma unroll
            for (int q = 0; q < 4; q++) acc[i][j][q] = 0.f;

    for (int kt = k0; kt < kend; kt += 16) {
        float4 av = *(const float4*)(A + (size_t)(m0 + mm) * lda + kt + kk);
        As[mm][kk + 0] = tf32r(av.x);
        As[mm][kk + 1] = tf32r(av.y);
        As[mm][kk + 2] = tf32r(av.z);
        As[mm][kk + 3] = tf32r(av.w);
        float4 wv = *(const float4*)(W + (size_t)(n0 + mm) * lda + kt + kk);
        Ws[mm][kk + 0] = tf32r(wv.x);
        Ws[mm][kk + 1] = tf32r(wv.y);
        Ws[mm][kk + 2] = tf32r(wv.z);
        Ws[mm][kk + 3] = tf32r(wv.w);
        __syncthreads();
#pragma unroll
        for (int ks = 0; ks < 16; ks += 8) {
            uint32_t af[2][4], bf[2][2];
#pragma unroll
            for (int mi = 0; mi < 2; mi++) {
                int r0 = wm + mi * 16 + g;
                af[mi][0] = __float_as_uint(As[r0    ][ks + tg]);
                af[mi][1] = __float_as_uint(As[r0 + 8][ks + tg]);
                af[mi][2] = __float_as_uint(As[r0    ][ks + tg + 4]);
                af[mi][3] = __float_as_uint(As[r0 + 8][ks + tg + 4]);
            }
#pragma unroll
            for (int ni = 0; ni < 2; ni++) {
                int rn = wn + ni * 8 + g;
                bf[ni][0] = __float_as_uint(Ws[rn][ks + tg]);
                bf[ni][1] = __float_as_uint(Ws[rn][ks + tg + 4]);
            }
#pragma unroll
            for (int mi = 0; mi < 2; mi++)
#pragma unroll
                for (int ni = 0; ni < 2; ni++)
                    MMA_TF32(acc[mi][ni], af[mi], bf[ni]);
        }
        __syncthreads();
    }
#pragma unroll
    for (int mi = 0; mi < 2; mi++) {
        int r0 = m0 + wm + mi * 16 + g;
#pragma unroll
        for (int ni = 0; ni < 2; ni++) {
            int col = n0 + wn + ni * 8 + 2 * tg;
            float c0 = acc[mi][ni][0], c1 = acc[mi][ni][1];
            float c2 = acc[mi][ni][2], c3 = acc[mi][ni][3];
            if (act < 2) {
                float b0v = bias[col], b1v = bias[col + 1];
                c0 += b0v; c1 += b1v; c2 += b0v; c3 += b1v;
                if (act == 1) {
                    c0 = gelu_exact(c0); c1 = gelu_exact(c1);
                    c2 = gelu_exact(c2); c3 = gelu_exact(c3);
                }
            }
            *(float2*)&out[(size_t)r0 * N2 + col]       = make_float2(c0, c1);
            *(float2*)&out[(size_t)(r0 + 8) * N2 + col] = make_float2(c2, c3);
        }
    }
}

// ====== bf16 GEMM1 (128 blocks) + We = Wo@WvT tf32 (64 blocks), one launch ==
__global__ __launch_bounds__(256) void gemm1_we_kernel(
    const __nv_bfloat16* __restrict__ A,
    const __nv_bfloat16* __restrict__ W,
    float* __restrict__ part,
    const float* __restrict__ Wo, int Kper) {
    __shared__ __nv_bfloat16 As[2][32][136];   // [k][m]
    __shared__ __nv_bfloat16 Ws[2][128][40];   // [n][k]
    __shared__ float AsF[64][20];
    __shared__ float WsF[64][20];
    int blk = blockIdx.x;
    int tid = threadIdx.x;

    if (blk >= 128) {
        // ---- We tile: We[n,k] = sum_d Wo[n,d] * WvT[k,d] ----
        int idx = blk - 128;
        tile_gemm64(Wo, g_WvT, nullptr, g_We, DM, DM,
                    (idx & 7) * 64, (idx >> 3) * 64, 0, DM, 2, AsF, WsF);
        return;
    }

    int m0 = (blk & 1) * 128;
    int n0 = ((blk >> 1) & 3) * 128;
    int z = blk >> 3;
    int k0 = z * Kper, kend = k0 + Kper;
    int w = tid >> 5, lane = tid & 31;
    int wm = (w >> 2) * 64, wn = (w & 3) * 32;
    int g = lane >> 2, tg = lane & 3;
    int lm_k = (lane & 7) + ((lane >> 4) << 3);   // 0..15
    int lm_m = (lane & 8);                        // 0 or 8

    float acc[4][4][4];
#pragma unroll
    for (int i = 0; i < 4; i++)
#pragma unroll
        for (int j = 0; j < 4; j++)
#pragma unroll
            for (int q = 0; q < 4; q++) acc[i][j][q] = 0.f;

    uint4 ra[2], rw[2];
    int a_kk[2], a_mq[2], w_nn, w_kq;
#pragma unroll
    for (int r = 0; r < 2; r++) {
        int idx = tid + 256 * r;
        a_kk[r] = idx >> 4;
        a_mq[r] = (idx & 15) << 3;
    }
    w_nn = tid >> 1;
    w_kq = (tid & 1) << 4;

#define G1_LDG(kt) do { \
    _Pragma("unroll") \
    for (int r = 0; r < 2; r++) \
        ra[r] = *(const uint4*)(A + (size_t)((kt) + a_kk[r]) * BB + m0 + a_mq[r]); \
    rw[0] = *(const uint4*)(W + (size_t)(n0 + w_nn) * NI + (kt) + w_kq); \
    rw[1] = *(const uint4*)(W + (size_t)(n0 + w_nn) * NI + (kt) + w_kq + 8); \
} while (0)

#define G1_STS(buf) do { \
    _Pragma("unroll") \
    for (int r = 0; r < 2; r++) \
        *(uint4*)&As[buf][a_kk[r]][a_mq[r]] = ra[r]; \
    *(uint4*)&Ws[buf][w_nn][w_kq] = rw[0]; \
    *(uint4*)&Ws[buf][w_nn][w_kq + 8] = rw[1]; \
} while (0)

    G1_LDG(k0);
    G1_STS(0);
    __syncthreads();

    int buf = 0;
    for (int kt = k0; kt < kend; kt += 32) {
        bool has_next = (kt + 32 < kend);
        if (has_next) G1_LDG(kt + 32);
#pragma unroll
        for (int kc = 0; kc < 32; kc += 16) {
            uint32_t af[4][4], bfr[4][2];
#pragma unroll
            for (int mi = 0; mi < 4; mi++) {
                uint32_t sa = (uint32_t)__cvta_generic_to_shared(
                    &As[buf][kc + lm_k][wm + mi * 16 + lm_m]);
                LDMATRIX_X4_TRANS(af[mi][0], af[mi][1], af[mi][2], af[mi][3], sa);
            }
#pragma unroll
            for (int ni = 0; ni < 4; ni++) {
                int rn = wn + ni * 8 + g;
                bfr[ni][0] = *(const uint32_t*)&Ws[buf][rn][kc + 2 * tg];
                bfr[ni][1] = *(const uint32_t*)&Ws[buf][rn][kc + 8 + 2 * tg];
            }
#pragma unroll
            for (int mi = 0; mi < 4; mi++)
#pragma unroll
                for (int ni = 0; ni < 4; ni++)
                    MMA_BF16(acc[mi][ni], af[mi], bfr[ni]);
        }
        if (has_next) G1_STS(buf ^ 1);
        __syncthreads();
        buf ^= 1;
    }
#undef G1_LDG
#undef G1_STS

    float* cp = part + (size_t)z * ((size_t)BB * DM);
#pragma unroll
    for (int mi = 0; mi < 4; mi++) {
        int r0 = m0 + wm + mi * 16 + g;
#pragma unroll
        for (int ni = 0; ni < 4; ni++) {
            int col = n0 + wn + ni * 8 + 2 * tg;
            *(float2*)&cp[(size_t)r0 * DM + col] =
                make_float2(acc[mi][ni][0], acc[mi][ni][1]);
            *(float2*)&cp[(size_t)(r0 + 8) * DM + col] =
                make_float2(acc[mi][ni][2], acc[mi][ni][3]);
        }
    }
}

// =========== bf16 loss GEMM: h2h[BB,DM] @ Wouth[NI,DM]^T + bias, MSE ========
__global__ __launch_bounds__(256) void gemm_loss_bf16_kernel(
    const __nv_bfloat16* __restrict__ A,
    const __nv_bfloat16* __restrict__ W,
    const float* __restrict__ bout,
    const float* __restrict__ x0,
    float* __restrict__ out) {
    __shared__ __nv_bfloat16 As[2][128][40];
    __shared__ __nv_bfloat16 Ws[2][128][40];
    __shared__ float sbuf[8];
    int m0 = blockIdx.x * 128;
    int n0 = blockIdx.y * 128;
    int tid = threadIdx.x;
    int w = tid >> 5, lane = tid & 31;
    int wm = (w >> 2) * 64, wn = (w & 3) * 32;
    int g = lane >> 2, tg = lane & 3;

    float acc[4][4][4];
#pragma unroll
    for (int i = 0; i < 4; i++)
#pragma unroll
        for (int j = 0; j < 4; j++)
#pragma unroll
            for (int q = 0; q < 4; q++) acc[i][j][q] = 0.f;

    int mm = tid >> 1;
    int kq = (tid & 1) << 4;
    uint4 ra[2], rw[2];

#define GL_LDG(kt) do { \
    ra[0] = *(const uint4*)(A + (size_t)(m0 + mm) * DM + (kt) + kq); \
    ra[1] = *(const uint4*)(A + (size_t)(m0 + mm) * DM + (kt) + kq + 8); \
    rw[0] = *(const uint4*)(W + (size_t)(n0 + mm) * DM + (kt) + kq); \
    rw[1] = *(const uint4*)(W + (size_t)(n0 + mm) * DM + (kt) + kq + 8); \
} while (0)

#define GL_STS(buf) do { \
    *(uint4*)&As[buf][mm][kq] = ra[0]; \
    *(uint4*)&As[buf][mm][kq + 8] = ra[1]; \
    *(uint4*)&Ws[buf][mm][kq] = rw[0]; \
    *(uint4*)&Ws[buf][mm][kq + 8] = rw[1]; \
} while (0)

    GL_LDG(0);
    GL_STS(0);
    __syncthreads();

    int buf = 0;
    for (int kt = 0; kt < DM; kt += 32) {
        bool has_next = (kt + 32 < DM);
        if (has_next) GL_LDG(kt + 32);
#pragma unroll
        for (int kc = 0; kc < 32; kc += 16) {
            uint32_t af[4][4], bfr[4][2];
#pragma unroll
            for (int mi = 0; mi < 4; mi++) {
                int r0 = wm + mi * 16 + g;
                af[mi][0] = *(const uint32_t*)&As[buf][r0    ][kc + 2 * tg];
                af[mi][1] = *(const uint32_t*)&As[buf][r0 + 8][kc + 2 * tg];
                af[mi][2] = *(const uint32_t*)&As[buf][r0    ][kc + 8 + 2 * tg];
                af[mi][3] = *(const uint32_t*)&As[buf][r0 + 8][kc + 8 + 2 * tg];
            }
#pragma unroll
            for (int ni = 0; ni < 4; ni++) {
                int rn = wn + ni * 8 + g;
                bfr[ni][0] = *(const uint32_t*)&Ws[buf][rn][kc + 2 * tg];
                bfr[ni][1] = *(const uint32_t*)&Ws[buf][rn][kc + 8 + 2 * tg];
            }
#pragma unroll
            for (int mi = 0; mi < 4; mi++)
#pragma unroll
                for (int ni = 0; ni < 4; ni++)
                    MMA_BF16(acc[mi][ni], af[mi], bfr[ni]);
        }
        if (has_next) GL_STS(buf ^ 1);
        __syncthreads();
        buf ^= 1;
    }
#undef GL_LDG
#undef GL_STS

    float local = 0.f;
#pragma unroll
    for (int ni = 0; ni < 4; ni++) {
        int col = n0 + wn + ni * 8 + 2 * tg;
        float bo0 = bout[col], bo1 = bout[col + 1];
#pragma unroll
        for (int mi = 0; mi < 4; mi++) {
            int r0 = m0 + wm + mi * 16 + g;
            float d00 = acc[mi][ni][0] + bo0 - x0[(size_t)r0 * NI + col];
            float d01 = acc[mi][ni][1] + bo1 - x0[(size_t)r0 * NI + col + 1];
            float d10 = acc[mi][ni][2] + bo0 - x0[(size_t)(r0 + 8) * NI + col];
            float d11 = acc[mi][ni][3] + bo1 - x0[(size_t)(r0 + 8) * NI + col + 1];
            local += d00 * d00 + d01 * d01 + d10 * d10 + d11 * d11;
        }
    }
#pragma unroll
    for (int o = 16; o > 0; o >>= 1) local += __shfl_xor_sync(0xffffffffu, local, o);
    if (lane == 0) sbuf[w] = local;
    __syncthreads();
    if (tid == 0) {
        float tot = 0.f;
#pragma unroll
        for (int i = 0; i < 8; i++) tot += sbuf[i];
        atomicAdd(out, tot * (1.f / ((float)BB * (float)NI)));
    }
}

// ================= fused middle section (persistent, grid-barrier) =========
__device__ __forceinline__ void gridbar(int i) {
    __syncthreads();
    if (threadIdx.x == 0) {
        __threadfence();
        atomicAdd(&g_bar[i], 1);
        while (atomicAdd(&g_bar[i], 0) < NCTA_MID) { }
    }
    __syncthreads();
}

// row layernorm helper: y0/y1 are this thread's 2 elems of a 512-row
__device__ __forceinline__ void ln_row(float y0, float y1,
                                       const float* __restrict__ g,
                                       const float* __restrict__ be,
                                       size_t base, float* sbuf,
                                       float* outf, __nv_bfloat16* outh) {
    int tid = threadIdx.x;
    __syncthreads();
    float s = y0 + y1;
#pragma unroll
    for (int o = 16; o > 0; o >>= 1) s += __shfl_xor_sync(0xffffffffu, s, o);
    if ((tid & 31) == 0) sbuf[tid >> 5] = s;
    __syncthreads();
    if (tid == 0) {
        float tot = 0.f;
        for (int i = 0; i < 8; i++) tot += sbuf[i];
        sbuf[0] = tot;
    }
    __syncthreads();
    float mu = sbuf[0] * (1.f / DM);
    __syncthreads();
    float d0 = y0 - mu, d1 = y1 - mu;
    float q = d0 * d0 + d1 * d1;
#pragma unroll
    for (int o = 16; o > 0; o >>= 1) q += __shfl_xor_sync(0xffffffffu, q, o);
    if ((tid & 31) == 0) sbuf[tid >> 5] = q;
    __syncthreads();
    if (tid == 0) {
        float tot = 0.f;
        for (int i = 0; i < 8; i++) tot += sbuf[i];
        sbuf[0] = tot;
    }
    __syncthreads();
    float inv = rsqrtf(sbuf[0] * (1.f / DM) + 1e-5f);
    float o0 = d0 * inv * g[tid] + be[tid];
    float o1 = d1 * inv * g[tid + 256] + be[tid + 256];
    if (outf) {
        outf[base + tid]       = o0;
        outf[base + tid + 256] = o1;
    } else {
        outh[base + tid]       = __float2bfloat16(o0);
        outh[base + tid + 256] = __float2bfloat16(o1);
    }
}

__global__ __launch_bounds__(256) void middle_kernel(
    const float* __restrict__ t,
    const float* __restrict__ Wt1, const float* __restrict__ bt1,
    const float* __restrict__ Wt2, const float* __restrict__ bt2,
    const float* __restrict__ b_in,
    const float* __restrict__ g1,  const float* __restrict__ be1,
    const float* __restrict__ Wf1, const float* __restrict__ bf1,
    const float* __restrict__ Wf2, const float* __restrict__ bf2,
    const float* __restrict__ g2,  const float* __restrict__ be2) {
    __shared__ float As[64][20];
    __shared__ float Ws[64][20];
    __shared__ float sh_u[64];
    __shared__ float sbuf[8];
    int cta = blockIdx.x, tid = threadIdx.x;

    // ---- P0: h = reduce16(part) + b_in + time embedding ----
    {
        int base = cta * 1024;            // 1024 elems per CTA (2 batch rows)
        if (tid < 64) {
            int bb = tid >> 5, j = tid & 31;
            float z = t[cta * 2 + bb] * Wt1[j] + bt1[j];
            sh_u[tid] = z / (1.f + expf(-z));   // silu
        }
        __syncthreads();
#pragma unroll
        for (int k = 0; k < 4; k++) {
            int i = base + k * 256 + tid;
            int d = i & 511;
            int bb = (i >> 9) & 1;
            float s = 0.f;
#pragma unroll
            for (int j = 0; j < NSP1; j++) s += g_part[(size_t)j * (BB * DM) + i];
            s += b_in[d];
            float te = bt2[d];
            const float* wr = Wt2 + d * 32;
#pragma unroll
            for (int j = 0; j < 32; j++) te += sh_u[bb * 32 + j] * wr[j];
            g_h[i] = s + te;
        }
    }
    gridbar(0);

    // ---- PA: attn partials = h @ We^T, split-K4 across all 128 CTAs ----
    {
        int sp = cta >> 5;
        int tile = cta & 31;
        tile_gemm64(g_h, g_We, nullptr, g_part + (size_t)sp * (BB * DM), DM, DM,
                    (tile & 3) * 64, (tile >> 2) * 64, sp * 128, sp * 128 + 128, 2,
                    As, Ws);
    }
    gridbar(1);

    // ---- PC: h1 = LN(h + reduce4(attn part) + bc)  (2 rows per CTA) ----
#pragma unroll
    for (int e = 0; e < 2; e++) {
        int r = cta * 2 + e;
        size_t base = (size_t)r * DM;
        size_t i0 = base + tid, i1 = base + tid + 256;
        float a0 = 0.f, a1 = 0.f;
#pragma unroll
        for (int j = 0; j < 4; j++) {
            a0 += __ldcg(&g_part[(size_t)j * (BB * DM) + i0]);   // P0 read these; PA rewrote
            a1 += __ldcg(&g_part[(size_t)j * (BB * DM) + i1]);
        }
        float y0 = g_h[i0] + a0 + g_bc[tid];
        float y1 = g_h[i1] + a1 + g_bc[tid + 256];
        ln_row(y0, y1, g1, be1, base, sbuf, g_h1, nullptr);
    }
    gridbar(2);

    // ---- PD: f1 = gelu(h1 @ Wf1^T + bf1)  (128 tiles, 1 per CTA) ----
    tile_gemm64(g_h1, Wf1, bf1, g_f1, DFF, DM,
                (cta & 3) * 64, (cta >> 2) * 64, 0, DM, 1, As, Ws);
    gridbar(3);

    // ---- PE: f2 partials = f1 @ Wf2^T (split-4, 128 tiles, 1 per CTA) ----
    {
        int sp = cta >> 5;
        int tile = cta & 31;
        tile_gemm64(g_f1, Wf2, nullptr, g_part + (size_t)sp * (BB * DM), DM, DFF,
                    (tile & 3) * 64, (tile >> 2) * 64, sp * 512, sp * 512 + 512, 2,
                    As, Ws);
    }
    gridbar(4);

    // ---- PF: h2 = LN(h1 + reduce4(part) + bf2) -> bf16  (2 rows per CTA) ----
#pragma unroll
    for (int e = 0; e < 2; e++) {
        int r = cta * 2 + e;
        size_t base = (size_t)r * DM;
        size_t i0 = base + tid, i1 = base + tid + 256;
        float s0 = 0.f, s1 = 0.f;
#pragma unroll
        for (int j = 0; j < 4; j++) {
            s0 += __ldcg(&g_part[(size_t)j * (BB * DM) + i0]);   // PC read these; PE rewrote
            s1 += __ldcg(&g_part[(size_t)j * (BB * DM) + i1]);
        }
        float y0 = __ldcg(&g_h1[i0]) + s0 + bf2[tid];
        float y1 = __ldcg(&g_h1[i1]) + s1 + bf2[tid + 256];
        ln_row(y0, y1, g2, be2, base, sbuf, nullptr, g_h2h);
    }

    // ---- ticket: last CTA resets barrier counters for next graph replay ----
    __syncthreads();
    if (tid == 0) {
        int old = atomicAdd(&g_bar[7], 1);
        if (old == NCTA_MID - 1) {
#pragma unroll
            for (int i = 0; i < 8; i++) atomicExch(&g_bar[i], 0);
        }
    }
}

// ---------------- launch ----------------
extern "C" void kernel_launch(void* const* d_in, const int* in_sizes, int n_in,
                              void* d_out, int out_size) {
    const float* x0    = (const float*)d_in[0];
    const float* t     = (const float*)d_in[1];
    const float* Lvals = (const float*)d_in[2];
    const float* W_in  = (const float*)d_in[3];
    const float* b_in  = (const float*)d_in[4];
    const float* W_out = (const float*)d_in[5];
    const float* b_out = (const float*)d_in[6];
    const float* W_qkv = (const float*)d_in[7];
    const float* b_qkv = (const float*)d_in[8];
    const float* W_o   = (const float*)d_in[9];
    const float* b_o   = (const float*)d_in[10];
    const float* g1    = (const float*)d_in[11];
    const float* be1   = (const float*)d_in[12];
    const float* g2    = (const float*)d_in[13];
    const float* be2   = (const float*)d_in[14];
    const float* W_f1  = (const float*)d_in[15];
    const float* b_f1  = (const float*)d_in[16];
    const float* W_f2  = (const float*)d_in[17];
    const float* b_f2  = (const float*)d_in[18];
    const float* W_t1  = (const float*)d_in[19];
    const float* b_t1  = (const float*)d_in[20];
    const float* W_t2  = (const float*)d_in[21];
    const float* b_t2  = (const float*)d_in[22];
    const int*   Lrows = (const int*)d_in[23];
    const int*   Lcols = (const int*)d_in[24];
    float* out = (float*)d_out;

    float *p_x0T, *p_part;
    __nv_bfloat16 *p_x0Th, *p_xth, *p_Winh, *p_Wouth, *p_h2h;
    int *p_off;
    int2* p_cpack;
    cudaGetSymbolAddress((void**)&p_x0T,  g_x0T);
    cudaGetSymbolAddress((void**)&p_x0Th, g_x0Th);
    cudaGetSymbolAddress((void**)&p_xth,  g_xth);
    cudaGetSymbolAddress((void**)&p_Winh, g_Winh);
    cudaGetSymbolAddress((void**)&p_Wouth,g_Wouth);
    cudaGetSymbolAddress((void**)&p_part, g_part);
    cudaGetSymbolAddress((void**)&p_h2h,  g_h2h);
    cudaGetSymbolAddress((void**)&p_off,  g_off);
    cudaGetSymbolAddress((void**)&p_cpack,g_cpack);

    // CSR build: one persistent kernel (hist, scans, apply, fill) + zero loss
    csr_kernel<<<NCTA_CSR, 256>>>(Lrows, Lcols, Lvals, out);

    // transpose x0 + weight cvt + WvT transpose + bc (one launch)
    transcvt_kernel<<<12545, 256>>>(x0, p_x0T, p_x0Th, W_in, p_Winh, W_out, p_Wouth,
                                    W_qkv + 2 * DM * DM,   // Wv
                                    W_o,
                                    b_qkv + 2 * DM,        // bv
                                    b_o);

    // xt (bf16) = x0T - tc*Lx
    gather_kernel<<<NI, 128>>>(p_x0T, p_x0Th, p_off, p_cpack, t, p_xth);

    // GEMM1 partials (bf16 tensor cores) + We = Wo@Wv (tf32, spare CTAs)
    gemm1_we_kernel<<<192, 256>>>(p_xth, p_Winh, p_part, W_o, NI / NSP1);

    // entire middle section in one persistent kernel (folded attention)
    middle_kernel<<<NCTA_MID, 256>>>(t, W_t1, b_t1, W_t2, b_t2, b_in,
                                     g1, be1, W_f1, b_f1, W_f2, b_f2, g2, be2);

    // loss = mean((h2 @ W_out^T + b_out - x0)^2)
    gemm_loss_bf16_kernel<<<dim3(2, NI / 128), 256>>>(p_h2h, p_Wouth, b_out, x0, out);
}

// round 14
// speedup vs baseline: 1.0413x; 1.0413x over previous
#include <cuda_runtime.h>
#include <cuda_bf16.h>
#include <math.h>
#include <stdint.h>

// Problem dims (fixed)
#define BB   256      // batch
#define NI   16384    // n_items
#define DM   512      // d_model
#define DFF  2048     // ff dim
#define NNZV (NI*33)  // 540672
#define NSP1 16       // K-splits for GEMM1
#define NCTA_MID 128  // CTAs in the fused middle kernel

// ---------------- scratch (device globals; no allocation allowed) ----------
__device__ float g_x0T[NI*BB];               // x0 transposed [N,B] fp32
__device__ __nv_bfloat16 g_x0Th[NI*BB];      // x0 transposed [N,B] bf16
__device__ __nv_bfloat16 g_xth[NI*BB];       // x_t [N,B] bf16 (k-major for GEMM1)
__device__ __nv_bfloat16 g_Winh[DM*NI];      // W_in bf16
__device__ __nv_bfloat16 g_Wouth[NI*DM];     // W_out bf16
__device__ float g_part[NSP1*BB*DM];         // split-K partials (reused)
__device__ float g_h  [BB*DM];
__device__ float g_h1 [BB*DM];
__device__ float g_f1 [BB*DFF];
__device__ __nv_bfloat16 g_h2h[BB*DM];       // h2 bf16 (only loss GEMM reads it)
// folded attention weights
__device__ float g_WvT[DM*DM];               // Wv transposed [k][d]
__device__ float g_We [DM*DM];               // We = Wo @ Wv, [n][k] row-major
__device__ float g_bc [DM];                  // bc = Wo @ bv + bo
// CSR build scratch
__device__ int   g_cnt[NI];       // zero-initialized; scan1 re-zeros each replay
__device__ int   g_off[NI + 1];
__device__ int   g_wp [NI];
__device__ int2  g_cpack[NNZV];   // packed (col, val_bits)
__device__ int   g_bsum[64];
// barrier counters for the fused middle kernel (reset by last CTA)
__device__ int   g_bar[8];

// ---------------- helpers ----------------
__device__ __forceinline__ float tf32r(float x) {
    uint32_t r;
    asm("cvt.rna.tf32.f32 %0, %1;" : "=r"(r) : "f"(x));
    return __uint_as_float(r);
}

__device__ __forceinline__ uint32_t bf2u(__nv_bfloat162 h) {
    uint32_t u;
    memcpy(&u, &h, 4);
    return u;
}

#define MMA_TF32(c, a, b) \
    asm volatile("mma.sync.aligned.m16n8k8.row.col.f32.tf32.tf32.f32 " \
                 "{%0,%1,%2,%3}, {%4,%5,%6,%7}, {%8,%9}, {%0,%1,%2,%3};" \
                 : "+f"((c)[0]), "+f"((c)[1]), "+f"((c)[2]), "+f"((c)[3]) \
                 : "r"((a)[0]), "r"((a)[1]), "r"((a)[2]), "r"((a)[3]), \
                   "r"((b)[0]), "r"((b)[1]))

#define MMA_BF16(c, a, b) \
    asm volatile("mma.sync.aligned.m16n8k16.row.col.f32.bf16.bf16.f32 " \
                 "{%0,%1,%2,%3}, {%4,%5,%6,%7}, {%8,%9}, {%0,%1,%2,%3};" \
                 : "+f"((c)[0]), "+f"((c)[1]), "+f"((c)[2]), "+f"((c)[3]) \
                 : "r"((a)[0]), "r"((a)[1]), "r"((a)[2]), "r"((a)[3]), \
                   "r"((b)[0]), "r"((b)[1]))

#define LDMATRIX_X4_TRANS(r0, r1, r2, r3, addr) \
    asm volatile("ldmatrix.sync.aligned.m8n8.x4.trans.shared.b16 {%0,%1,%2,%3}, [%4];" \
                 : "=r"(r0), "=r"(r1), "=r"(r2), "=r"(r3) : "r"(addr))

__device__ __forceinline__ float gelu_exact(float s) {
    return 0.5f * s * (1.f + erff(s * 0.70710678118654752f));
}

// ---------------- CSR build (4 wide launches — max parallelism) -------------
__global__ void hist_kernel(const int* __restrict__ rows, int* __restrict__ cnt) {
    int i = blockIdx.x * blockDim.x + threadIdx.x;
    if (i < NNZV) atomicAdd(&cnt[rows[i]], 1);
}

// per-block (256 bins) exclusive scan, write block totals; resets cnt to 0
__global__ void scan1_kernel(int* __restrict__ cnt, int* __restrict__ off,
                             int* __restrict__ bsum) {
    __shared__ int ws[8];
    int tid = threadIdx.x;
    int i = blockIdx.x * 256 + tid;
    int c = cnt[i];
    cnt[i] = 0;                       // reset for next replay
    int lane = tid & 31, w = tid >> 5;
    int inc = c;
#pragma unroll
    for (int o = 1; o < 32; o <<= 1) {
        int v = __shfl_up_sync(0xffffffffu, inc, o);
        if (lane >= o) inc += v;
    }
    if (lane == 31) ws[w] = inc;
    __syncthreads();
    if (tid < 8) {
        int v = ws[tid];
#pragma unroll
        for (int o = 1; o < 8; o <<= 1) {
            int u = __shfl_up_sync(0xffu, v, o);
            if (tid >= o) v += u;
        }
        ws[tid] = v;
    }
    __syncthreads();
    int base = (w > 0) ? ws[w - 1] : 0;
    off[i] = base + inc - c;
    if (tid == 255) bsum[blockIdx.x] = ws[7];
}

// merged scan2+scan3: scan 64 block sums, apply to off, copy to wp, zero loss
__global__ void scan23_kernel(const int* __restrict__ bsum,
                              int* __restrict__ off, int* __restrict__ wp,
                              float* __restrict__ loss) {
    __shared__ int sb[64];
    __shared__ int ws[2];
    int tid = threadIdx.x;   // 1024
    int lane = tid & 31;
    int v = 0, inc = 0;
    if (tid < 64) {
        v = bsum[tid];
        inc = v;
#pragma unroll
        for (int o = 1; o < 32; o <<= 1) {
            int u = __shfl_up_sync(0xffffffffu, inc, o);
            if (lane >= o) inc += u;
        }
        if (lane == 31) ws[tid >> 5] = inc;
    }
    __syncthreads();
    if (tid < 64) {
        int base = (tid >= 32) ? ws[0] : 0;
        sb[tid] = base + inc - v;
    }
    if (tid == 0) *loss = 0.f;
    __syncthreads();
    if (tid == 0) off[NI] = ws[0] + ws[1];
#pragma unroll
    for (int it = 0; it < 16; it++) {
        int i = it * 1024 + tid;
        int val = off[i] + sb[i >> 8];
        off[i] = val;
        wp[i] = val;
    }
}

__global__ void fill_kernel(const int* __restrict__ rows, const int* __restrict__ cols,
                            const float* __restrict__ vals,
                            int* __restrict__ wp, int2* __restrict__ cpack) {
    int i = blockIdx.x * blockDim.x + threadIdx.x;
    if (i >= NNZV) return;
    int r = rows[i];
    int p = atomicAdd(&wp[r], 1);
    cpack[p] = make_int2(cols[i], __float_as_int(vals[i]));
}

// ------- merged transpose (x0, Wv) + weight cvt + bc = Wo@bv + bo ----------
__global__ void transcvt_kernel(const float* __restrict__ x,
                                float* __restrict__ xt,
                                __nv_bfloat16* __restrict__ xh,
                                const float* __restrict__ wa, __nv_bfloat16* __restrict__ oa,
                                const float* __restrict__ wb, __nv_bfloat16* __restrict__ ob,
                                const float* __restrict__ Wv,
                                const float* __restrict__ Wo,
                                const float* __restrict__ bv,
                                const float* __restrict__ bo) {
    __shared__ float s[32][33];
    int blk = blockIdx.x, tid = threadIdx.x;
    if (blk < 4096) {
        // x0 [B,N] -> x0T [N,B] fp32 + bf16
        int n0 = (blk & 511) * 32, b0 = (blk >> 9) * 32;
        int tx = tid & 31, ty = tid >> 5;
#pragma unroll
        for (int i = 0; i < 32; i += 8)
            s[ty + i][tx] = x[(size_t)(b0 + ty + i) * NI + n0 + tx];
        __syncthreads();
#pragma unroll
        for (int i = 0; i < 32; i += 8) {
            float val = s[tx][ty + i];
            size_t idx = (size_t)(n0 + ty + i) * BB + b0 + tx;
            xt[idx] = val;
            xh[idx] = __float2bfloat16(val);
        }
    } else if (blk < 12288) {
        // W_in / W_out fp32 -> bf16
        int blk2 = blk - 4096;
        const float* src;
        __nv_bfloat16* dst;
        size_t base;
        if (blk2 < 4096) { src = wa; dst = oa; base = (size_t)blk2 * 2048; }
        else             { src = wb; dst = ob; base = (size_t)(blk2 - 4096) * 2048; }
        size_t i = base + tid * 8;
        float4 v0 = *(const float4*)(src + i);
        float4 v1 = *(const float4*)(src + i + 4);
        uint4 o;
        o.x = bf2u(__floats2bfloat162_rn(v0.x, v0.y));
        o.y = bf2u(__floats2bfloat162_rn(v0.z, v0.w));
        o.z = bf2u(__floats2bfloat162_rn(v1.x, v1.y));
        o.w = bf2u(__floats2bfloat162_rn(v1.z, v1.w));
        *(uint4*)(dst + i) = o;
    } else if (blk < 12544) {
        // Wv [d][k] -> WvT [k][d]  (32x32 tiles)
        int idx = blk - 12288;
        int k0 = (idx & 15) * 32, d0 = (idx >> 4) * 32;
        int tx = tid & 31, ty = tid >> 5;
#pragma unroll
        for (int i = 0; i < 32; i += 8)
            s[ty + i][tx] = Wv[(size_t)(d0 + ty + i) * DM + k0 + tx];
        __syncthreads();
#pragma unroll
        for (int i = 0; i < 32; i += 8)
            g_WvT[(size_t)(k0 + ty + i) * DM + d0 + tx] = s[tx][ty + i];
    } else {
        // bc[n] = sum_d Wo[n,d]*bv[d] + bo[n]   (warp per row)
        int w = tid >> 5, lane = tid & 31;
        for (int n = w; n < DM; n += 8) {
            float acc = 0.f;
            const float* wr = Wo + (size_t)n * DM;
            for (int d = lane; d < DM; d += 32) acc += wr[d] * bv[d];
#pragma unroll
            for (int o = 16; o > 0; o >>= 1) acc += __shfl_xor_sync(0xffffffffu, acc, o);
            if (lane == 0) g_bc[n] = acc + bo[n];
        }
    }
}

// ---------------- gather: xth[r,:] = bf16(x0T[r,:] - tc[:]*sum val*x0Th[col,:]) --
__global__ void gather_kernel(const float* __restrict__ x0T,
                              const __nv_bfloat16* __restrict__ x0Th,
                              const int* __restrict__ off,
                              const int2* __restrict__ cpack,
                              const float* __restrict__ t,
                              __nv_bfloat16* __restrict__ xth) {
    int r = blockIdx.x;
    int tid = threadIdx.x;        // 0..127
    int b2 = tid * 2;
    int s = off[r], e = off[r + 1];
    float acc0 = 0.f, acc1 = 0.f;
    int j = s;
    for (; j + 3 < e; j += 4) {
        int2 cv0 = __ldg(&cpack[j]),     cv1 = __ldg(&cpack[j + 1]);
        int2 cv2 = __ldg(&cpack[j + 2]), cv3 = __ldg(&cpack[j + 3]);
        float v0 = __int_as_float(cv0.y), v1 = __int_as_float(cv1.y);
        float v2 = __int_as_float(cv2.y), v3 = __int_as_float(cv3.y);
        float2 f0 = __bfloat1622float2(*(const __nv_bfloat162*)(x0Th + (size_t)cv0.x * BB + b2));
        float2 f1 = __bfloat1622float2(*(const __nv_bfloat162*)(x0Th + (size_t)cv1.x * BB + b2));
        float2 f2 = __bfloat1622float2(*(const __nv_bfloat162*)(x0Th + (size_t)cv2.x * BB + b2));
        float2 f3 = __bfloat1622float2(*(const __nv_bfloat162*)(x0Th + (size_t)cv3.x * BB + b2));
        acc0 += v0 * f0.x + v1 * f1.x + v2 * f2.x + v3 * f3.x;
        acc1 += v0 * f0.y + v1 * f1.y + v2 * f2.y + v3 * f3.y;
    }
    for (; j < e; j++) {
        int2 cv0 = __ldg(&cpack[j]);
        float v0 = __int_as_float(cv0.y);
        float2 f0 = __bfloat1622float2(*(const __nv_bfloat162*)(x0Th + (size_t)cv0.x * BB + b2));
        acc0 += v0 * f0.x;
        acc1 += v0 * f0.y;
    }
    float tc0 = 0.5f * t[b2];
    float tc1 = 0.5f * t[b2 + 1];
    float2 xv = *(const float2*)(x0T + (size_t)r * BB + b2);
    __nv_bfloat162 ov = __floats2bfloat162_rn(xv.x - tc0 * acc0, xv.y - tc1 * acc1);
    *(__nv_bfloat162*)(xth + (size_t)r * BB + b2) = ov;
}

// 64x64 TF32 tile GEMM with 256 threads (8 warps, 2m x 4n, warp 32x16).
// act: 0 = +bias, 1 = +bias+gelu, 2 = raw store (partials)
__device__ __noinline__ void tile_gemm64(const float* __restrict__ A,
                                         const float* __restrict__ W,
                                         const float* __restrict__ bias,
                                         float* __restrict__ out,
                                         int N2, int lda, int m0, int n0,
                                         int k0, int kend, int act,
                                         float As[][20], float Ws[][20]) {
    int tid = threadIdx.x;
    int w = tid >> 5, lane = tid & 31;
    int wm = (w >> 2) * 32, wn = (w & 3) * 16;
    int g = lane >> 2, tg = lane & 3;
    int mm = tid >> 2, kk = (tid & 3) * 4;

    float acc[2][2][4];
#pragma unroll
    for (int i = 0; i < 2; i++)
#pragma unroll
        for (int j = 0; j < 2; j++)
#pragma unroll
            for (int q = 0; q < 4; q++) acc[i][j][q] = 0.f;

    for (int kt = k0; kt < kend; kt += 16) {
        float4 av = *(const float4*)(A + (size_t)(m0 + mm) * lda + kt + kk);
        As[mm][kk + 0] = tf32r(av.x);
        As[mm][kk + 1] = tf32r(av.y);
        As[mm][kk + 2] = tf32r(av.z);
        As[mm][kk + 3] = tf32r(av.w);
        float4 wv = *(const float4*)(W + (size_t)(n0 + mm) * lda + kt + kk);
        Ws[mm][kk + 0] = tf32r(wv.x);
        Ws[mm][kk + 1] = tf32r(wv.y);
        Ws[mm][kk + 2] = tf32r(wv.z);
        Ws[mm][kk + 3] = tf32r(wv.w);
        __syncthreads();
#pragma unroll
        for (int ks = 0; ks < 16; ks += 8) {
            uint32_t af[2][4], bf[2][2];
#pragma unroll
            for (int mi = 0; mi < 2; mi++) {
                int r0 = wm + mi * 16 + g;
                af[mi][0] = __float_as_uint(As[r0    ][ks + tg]);
                af[mi][1] = __float_as_uint(As[r0 + 8][ks + tg]);
                af[mi][2] = __float_as_uint(As[r0    ][ks + tg + 4]);
                af[mi][3] = __float_as_uint(As[r0 + 8][ks + tg + 4]);
            }
#pragma unroll
            for (int ni = 0; ni < 2; ni++) {
                int rn = wn + ni * 8 + g;
                bf[ni][0] = __float_as_uint(Ws[rn][ks + tg]);
                bf[ni][1] = __float_as_uint(Ws[rn][ks + tg + 4]);
            }
#pragma unroll
            for (int mi = 0; mi < 2; mi++)
#pragma unroll
                for (int ni = 0; ni < 2; ni++)
                    MMA_TF32(acc[mi][ni], af[mi], bf[ni]);
        }
        __syncthreads();
    }
#pragma unroll
    for (int mi = 0; mi < 2; mi++) {
        int r0 = m0 + wm + mi * 16 + g;
#pragma unroll
        for (int ni = 0; ni < 2; ni++) {
            int col = n0 + wn + ni * 8 + 2 * tg;
            float c0 = acc[mi][ni][0], c1 = acc[mi][ni][1];
            float c2 = acc[mi][ni][2], c3 = acc[mi][ni][3];
            if (act < 2) {
                float b0v = bias[col], b1v = bias[col + 1];
                c0 += b0v; c1 += b1v; c2 += b0v; c3 += b1v;
                if (act == 1) {
                    c0 = gelu_exact(c0); c1 = gelu_exact(c1);
                    c2 = gelu_exact(c2); c3 = gelu_exact(c3);
                }
            }
            *(float2*)&out[(size_t)r0 * N2 + col]       = make_float2(c0, c1);
            *(float2*)&out[(size_t)(r0 + 8) * N2 + col] = make_float2(c2, c3);
        }
    }
}

// ====== bf16 GEMM1 (128 blocks) + We = Wo@WvT tf32 (64 blocks), one launch ==
// SMEM for the two paths is ALIASED (union) to keep footprint at 37.9 KB.
#define G1_SMEM_BYTES (2*32*136*2 + 2*128*40*2)   // 17408 + 20480 = 37888
__global__ __launch_bounds__(256) void gemm1_we_kernel(
    const __nv_bfloat16* __restrict__ A,
    const __nv_bfloat16* __restrict__ W,
    float* __restrict__ part,
    const float* __restrict__ Wo, int Kper) {
    __shared__ __align__(16) char smem_raw[G1_SMEM_BYTES];
    int blk = blockIdx.x;
    int tid = threadIdx.x;

    if (blk >= 128) {
        // ---- We tile: We[n,k] = sum_d Wo[n,d] * WvT[k,d]  (aliased smem) ----
        float (*AsF)[20] = reinterpret_cast<float(*)[20]>(smem_raw);
        float (*WsF)[20] = reinterpret_cast<float(*)[20]>(smem_raw + 64 * 20 * 4);
        int idx = blk - 128;
        tile_gemm64(Wo, g_WvT, nullptr, g_We, DM, DM,
                    (idx & 7) * 64, (idx >> 3) * 64, 0, DM, 2, AsF, WsF);
        return;
    }

    __nv_bfloat16 (*As)[32][136] =
        reinterpret_cast<__nv_bfloat16(*)[32][136]>(smem_raw);
    __nv_bfloat16 (*Ws)[128][40] =
        reinterpret_cast<__nv_bfloat16(*)[128][40]>(smem_raw + 2 * 32 * 136 * 2);

    int m0 = (blk & 1) * 128;
    int n0 = ((blk >> 1) & 3) * 128;
    int z = blk >> 3;
    int k0 = z * Kper, kend = k0 + Kper;
    int w = tid >> 5, lane = tid & 31;
    int wm = (w >> 2) * 64, wn = (w & 3) * 32;
    int g = lane >> 2, tg = lane & 3;
    int lm_k = (lane & 7) + ((lane >> 4) << 3);   // 0..15
    int lm_m = (lane & 8);                        // 0 or 8

    float acc[4][4][4];
#pragma unroll
    for (int i = 0; i < 4; i++)
#pragma unroll
        for (int j = 0; j < 4; j++)
#pragma unroll
            for (int q = 0; q < 4; q++) acc[i][j][q] = 0.f;

    uint4 ra[2], rw[2];
    int a_kk[2], a_mq[2], w_nn, w_kq;
#pragma unroll
    for (int r = 0; r < 2; r++) {
        int idx = tid + 256 * r;
        a_kk[r] = idx >> 4;
        a_mq[r] = (idx & 15) << 3;
    }
    w_nn = tid >> 1;
    w_kq = (tid & 1) << 4;

#define G1_LDG(kt) do { \
    _Pragma("unroll") \
    for (int r = 0; r < 2; r++) \
        ra[r] = *(const uint4*)(A + (size_t)((kt) + a_kk[r]) * BB + m0 + a_mq[r]); \
    rw[0] = *(const uint4*)(W + (size_t)(n0 + w_nn) * NI + (kt) + w_kq); \
    rw[1] = *(const uint4*)(W + (size_t)(n0 + w_nn) * NI + (kt) + w_kq + 8); \
} while (0)

#define G1_STS(buf) do { \
    _Pragma("unroll") \
    for (int r = 0; r < 2; r++) \
        *(uint4*)&As[buf][a_kk[r]][a_mq[r]] = ra[r]; \
    *(uint4*)&Ws[buf][w_nn][w_kq] = rw[0]; \
    *(uint4*)&Ws[buf][w_nn][w_kq + 8] = rw[1]; \
} while (0)

    G1_LDG(k0);
    G1_STS(0);
    __syncthreads();

    int buf = 0;
    for (int kt = k0; kt < kend; kt += 32) {
        bool has_next = (kt + 32 < kend);
        if (has_next) G1_LDG(kt + 32);
#pragma unroll
        for (int kc = 0; kc < 32; kc += 16) {
            uint32_t af[4][4], bfr[4][2];
#pragma unroll
            for (int mi = 0; mi < 4; mi++) {
                uint32_t sa = (uint32_t)__cvta_generic_to_shared(
                    &As[buf][kc + lm_k][wm + mi * 16 + lm_m]);
                LDMATRIX_X4_TRANS(af[mi][0], af[mi][1], af[mi][2], af[mi][3], sa);
            }
#pragma unroll
            for (int ni = 0; ni < 4; ni++) {
                int rn = wn + ni * 8 + g;
                bfr[ni][0] = *(const uint32_t*)&Ws[buf][rn][kc + 2 * tg];
                bfr[ni][1] = *(const uint32_t*)&Ws[buf][rn][kc + 8 + 2 * tg];
            }
#pragma unroll
            for (int mi = 0; mi < 4; mi++)
#pragma unroll
                for (int ni = 0; ni < 4; ni++)
                    MMA_BF16(acc[mi][ni], af[mi], bfr[ni]);
        }
        if (has_next) G1_STS(buf ^ 1);
        __syncthreads();
        buf ^= 1;
    }
#undef G1_LDG
#undef G1_STS

    float* cp = part + (size_t)z * ((size_t)BB * DM);
#pragma unroll
    for (int mi = 0; mi < 4; mi++) {
        int r0 = m0 + wm + mi * 16 + g;
#pragma unroll
        for (int ni = 0; ni < 4; ni++) {
            int col = n0 + wn + ni * 8 + 2 * tg;
            *(float2*)&cp[(size_t)r0 * DM + col] =
                make_float2(acc[mi][ni][0], acc[mi][ni][1]);
            *(float2*)&cp[(size_t)(r0 + 8) * DM + col] =
                make_float2(acc[mi][ni][2], acc[mi][ni][3]);
        }
    }
}

// =========== bf16 loss GEMM: h2h[BB,DM] @ Wouth[NI,DM]^T + bias, MSE ========
__global__ __launch_bounds__(256) void gemm_loss_bf16_kernel(
    const __nv_bfloat16* __restrict__ A,
    const __nv_bfloat16* __restrict__ W,
    const float* __restrict__ bout,
    const float* __restrict__ x0,
    float* __restrict__ out) {
    __shared__ __nv_bfloat16 As[2][128][40];
    __shared__ __nv_bfloat16 Ws[2][128][40];
    __shared__ float sbuf[8];
    int m0 = blockIdx.x * 128;
    int n0 = blockIdx.y * 128;
    int tid = threadIdx.x;
    int w = tid >> 5, lane = tid & 31;
    int wm = (w >> 2) * 64, wn = (w & 3) * 32;
    int g = lane >> 2, tg = lane & 3;

    float acc[4][4][4];
#pragma unroll
    for (int i = 0; i < 4; i++)
#pragma unroll
        for (int j = 0; j < 4; j++)
#pragma unroll
            for (int q = 0; q < 4; q++) acc[i][j][q] = 0.f;

    int mm = tid >> 1;
    int kq = (tid & 1) << 4;
    uint4 ra[2], rw[2];

#define GL_LDG(kt) do { \
    ra[0] = *(const uint4*)(A + (size_t)(m0 + mm) * DM + (kt) + kq); \
    ra[1] = *(const uint4*)(A + (size_t)(m0 + mm) * DM + (kt) + kq + 8); \
    rw[0] = *(const uint4*)(W + (size_t)(n0 + mm) * DM + (kt) + kq); \
    rw[1] = *(const uint4*)(W + (size_t)(n0 + mm) * DM + (kt) + kq + 8); \
} while (0)

#define GL_STS(buf) do { \
    *(uint4*)&As[buf][mm][kq] = ra[0]; \
    *(uint4*)&As[buf][mm][kq + 8] = ra[1]; \
    *(uint4*)&Ws[buf][mm][kq] = rw[0]; \
    *(uint4*)&Ws[buf][mm][kq + 8] = rw[1]; \
} while (0)

    GL_LDG(0);
    GL_STS(0);
    __syncthreads();

    int buf = 0;
    for (int kt = 0; kt < DM; kt += 32) {
        bool has_next = (kt + 32 < DM);
        if (has_next) GL_LDG(kt + 32);
#pragma unroll
        for (int kc = 0; kc < 32; kc += 16) {
            uint32_t af[4][4], bfr[4][2];
#pragma unroll
            for (int mi = 0; mi < 4; mi++) {
                int r0 = wm + mi * 16 + g;
                af[mi][0] = *(const uint32_t*)&As[buf][r0    ][kc + 2 * tg];
                af[mi][1] = *(const uint32_t*)&As[buf][r0 + 8][kc + 2 * tg];
                af[mi][2] = *(const uint32_t*)&As[buf][r0    ][kc + 8 + 2 * tg];
                af[mi][3] = *(const uint32_t*)&As[buf][r0 + 8][kc + 8 + 2 * tg];
            }
#pragma unroll
            for (int ni = 0; ni < 4; ni++) {
                int rn = wn + ni * 8 + g;
                bfr[ni][0] = *(const uint32_t*)&Ws[buf][rn][kc + 2 * tg];
                bfr[ni][1] = *(const uint32_t*)&Ws[buf][rn][kc + 8 + 2 * tg];
            }
#pragma unroll
            for (int mi = 0; mi < 4; mi++)
#pragma unroll
                for (int ni = 0; ni < 4; ni++)
                    MMA_BF16(acc[mi][ni], af[mi], bfr[ni]);
        }
        if (has_next) GL_STS(buf ^ 1);
        __syncthreads();
        buf ^= 1;
    }
#undef GL_LDG
#undef GL_STS

    float local = 0.f;
#pragma unroll
    for (int ni = 0; ni < 4; ni++) {
        int col = n0 + wn + ni * 8 + 2 * tg;
        float bo0 = bout[col], bo1 = bout[col + 1];
#pragma unroll
        for (int mi = 0; mi < 4; mi++) {
            int r0 = m0 + wm + mi * 16 + g;
            float d00 = acc[mi][ni][0] + bo0 - x0[(size_t)r0 * NI + col];
            float d01 = acc[mi][ni][1] + bo1 - x0[(size_t)r0 * NI + col + 1];
            float d10 = acc[mi][ni][2] + bo0 - x0[(size_t)(r0 + 8) * NI + col];
            float d11 = acc[mi][ni][3] + bo1 - x0[(size_t)(r0 + 8) * NI + col + 1];
            local += d00 * d00 + d01 * d01 + d10 * d10 + d11 * d11;
        }
    }
#pragma unroll
    for (int o = 16; o > 0; o >>= 1) local += __shfl_xor_sync(0xffffffffu, local, o);
    if (lane == 0) sbuf[w] = local;
    __syncthreads();
    if (tid == 0) {
        float tot = 0.f;
#pragma unroll
        for (int i = 0; i < 8; i++) tot += sbuf[i];
        atomicAdd(out, tot * (1.f / ((float)BB * (float)NI)));
    }
}

// ================= fused middle section (persistent, grid-barrier) =========
__device__ __forceinline__ void gridbar(int i) {
    __syncthreads();
    if (threadIdx.x == 0) {
        __threadfence();
        atomicAdd(&g_bar[i], 1);
        while (atomicAdd(&g_bar[i], 0) < NCTA_MID) { }
    }
    __syncthreads();
}

// row layernorm helper: y0/y1 are this thread's 2 elems of a 512-row
__device__ __forceinline__ void ln_row(float y0, float y1,
                                       const float* __restrict__ g,
                                       const float* __restrict__ be,
                                       size_t base, float* sbuf,
                                       float* outf, __nv_bfloat16* outh) {
    int tid = threadIdx.x;
    __syncthreads();
    float s = y0 + y1;
#pragma unroll
    for (int o = 16; o > 0; o >>= 1) s += __shfl_xor_sync(0xffffffffu, s, o);
    if ((tid & 31) == 0) sbuf[tid >> 5] = s;
    __syncthreads();
    if (tid == 0) {
        float tot = 0.f;
        for (int i = 0; i < 8; i++) tot += sbuf[i];
        sbuf[0] = tot;
    }
    __syncthreads();
    float mu = sbuf[0] * (1.f / DM);
    __syncthreads();
    float d0 = y0 - mu, d1 = y1 - mu;
    float q = d0 * d0 + d1 * d1;
#pragma unroll
    for (int o = 16; o > 0; o >>= 1) q += __shfl_xor_sync(0xffffffffu, q, o);
    if ((tid & 31) == 0) sbuf[tid >> 5] = q;
    __syncthreads();
    if (tid == 0) {
        float tot = 0.f;
        for (int i = 0; i < 8; i++) tot += sbuf[i];
        sbuf[0] = tot;
    }
    __syncthreads();
    float inv = rsqrtf(sbuf[0] * (1.f / DM) + 1e-5f);
    float o0 = d0 * inv * g[tid] + be[tid];
    float o1 = d1 * inv * g[tid + 256] + be[tid + 256];
    if (outf) {
        outf[base + tid]       = o0;
        outf[base + tid + 256] = o1;
    } else {
        outh[base + tid]       = __float2bfloat16(o0);
        outh[base + tid + 256] = __float2bfloat16(o1);
    }
}

__global__ __launch_bounds__(256) void middle_kernel(
    const float* __restrict__ t,
    const float* __restrict__ Wt1, const float* __restrict__ bt1,
    const float* __restrict__ Wt2, const float* __restrict__ bt2,
    const float* __restrict__ b_in,
    const float* __restrict__ g1,  const float* __restrict__ be1,
    const float* __restrict__ Wf1, const float* __restrict__ bf1,
    const float* __restrict__ Wf2, const float* __restrict__ bf2,
    const float* __restrict__ g2,  const float* __restrict__ be2) {
    __shared__ float As[64][20];
    __shared__ float Ws[64][20];
    __shared__ float sh_u[64];
    __shared__ float sbuf[8];
    int cta = blockIdx.x, tid = threadIdx.x;

    // ---- P0: h = reduce16(part) + b_in + time embedding ----
    {
        int base = cta * 1024;            // 1024 elems per CTA (2 batch rows)
        if (tid < 64) {
            int bb = tid >> 5, j = tid & 31;
            float z = t[cta * 2 + bb] * Wt1[j] + bt1[j];
            sh_u[tid] = z / (1.f + expf(-z));   // silu
        }
        __syncthreads();
#pragma unroll
        for (int k = 0; k < 4; k++) {
            int i = base + k * 256 + tid;
            int d = i & 511;
            int bb = (i >> 9) & 1;
            float s = 0.f;
#pragma unroll
            for (int j = 0; j < NSP1; j++) s += g_part[(size_t)j * (BB * DM) + i];
            s += b_in[d];
            float te = bt2[d];
            const float* wr = Wt2 + d * 32;
#pragma unroll
            for (int j = 0; j < 32; j++) te += sh_u[bb * 32 + j] * wr[j];
            g_h[i] = s + te;
        }
    }
    gridbar(0);

    // ---- PA: attn partials = h @ We^T, split-K4 across all 128 CTAs ----
    {
        int sp = cta >> 5;
        int tile = cta & 31;
        tile_gemm64(g_h, g_We, nullptr, g_part + (size_t)sp * (BB * DM), DM, DM,
                    (tile & 3) * 64, (tile >> 2) * 64, sp * 128, sp * 128 + 128, 2,
                    As, Ws);
    }
    gridbar(1);

    // ---- PC: h1 = LN(h + reduce4(attn part) + bc)  (2 rows per CTA) ----
#pragma unroll
    for (int e = 0; e < 2; e++) {
        int r = cta * 2 + e;
        size_t base = (size_t)r * DM;
        size_t i0 = base + tid, i1 = base + tid + 256;
        float a0 = 0.f, a1 = 0.f;
#pragma unroll
        for (int j = 0; j < 4; j++) {
            a0 += __ldcg(&g_part[(size_t)j * (BB * DM) + i0]);   // P0 read these; PA rewrote
            a1 += __ldcg(&g_part[(size_t)j * (BB * DM) + i1]);
        }
        float y0 = g_h[i0] + a0 + g_bc[tid];
        float y1 = g_h[i1] + a1 + g_bc[tid + 256];
        ln_row(y0, y1, g1, be1, base, sbuf, g_h1, nullptr);
    }
    gridbar(2);

    // ---- PD: f1 = gelu(h1 @ Wf1^T + bf1)  (128 tiles, 1 per CTA) ----
    tile_gemm64(g_h1, Wf1, bf1, g_f1, DFF, DM,
                (cta & 3) * 64, (cta >> 2) * 64, 0, DM, 1, As, Ws);
    gridbar(3);

    // ---- PE: f2 partials = f1 @ Wf2^T (split-4, 128 tiles, 1 per CTA) ----
    {
        int sp = cta >> 5;
        int tile = cta & 31;
        tile_gemm64(g_f1, Wf2, nullptr, g_part + (size_t)sp * (BB * DM), DM, DFF,
                    (tile & 3) * 64, (tile >> 2) * 64, sp * 512, sp * 512 + 512, 2,
                    As, Ws);
    }
    gridbar(4);

    // ---- PF: h2 = LN(h1 + reduce4(part) + bf2) -> bf16  (2 rows per CTA) ----
#pragma unroll
    for (int e = 0; e < 2; e++) {
        int r = cta * 2 + e;
        size_t base = (size_t)r * DM;
        size_t i0 = base + tid, i1 = base + tid + 256;
        float s0 = 0.f, s1 = 0.f;
#pragma unroll
        for (int j = 0; j < 4; j++) {
            s0 += __ldcg(&g_part[(size_t)j * (BB * DM) + i0]);   // PC read these; PE rewrote
            s1 += __ldcg(&g_part[(size_t)j * (BB * DM) + i1]);
        }
        float y0 = __ldcg(&g_h1[i0]) + s0 + bf2[tid];
        float y1 = __ldcg(&g_h1[i1]) + s1 + bf2[tid + 256];
        ln_row(y0, y1, g2, be2, base, sbuf, nullptr, g_h2h);
    }

    // ---- ticket: last CTA resets barrier counters for next graph replay ----
    __syncthreads();
    if (tid == 0) {
        int old = atomicAdd(&g_bar[7], 1);
        if (old == NCTA_MID - 1) {
#pragma unroll
            for (int i = 0; i < 8; i++) atomicExch(&g_bar[i], 0);
        }
    }
}

// ---------------- launch ----------------
extern "C" void kernel_launch(void* const* d_in, const int* in_sizes, int n_in,
                              void* d_out, int out_size) {
    const float* x0    = (const float*)d_in[0];
    const float* t     = (const float*)d_in[1];
    const float* Lvals = (const float*)d_in[2];
    const float* W_in  = (const float*)d_in[3];
    const float* b_in  = (const float*)d_in[4];
    const float* W_out = (const float*)d_in[5];
    const float* b_out = (const float*)d_in[6];
    const float* W_qkv = (const float*)d_in[7];
    const float* b_qkv = (const float*)d_in[8];
    const float* W_o   = (const float*)d_in[9];
    const float* b_o   = (const float*)d_in[10];
    const float* g1    = (const float*)d_in[11];
    const float* be1   = (const float*)d_in[12];
    const float* g2    = (const float*)d_in[13];
    const float* be2   = (const float*)d_in[14];
    const float* W_f1  = (const float*)d_in[15];
    const float* b_f1  = (const float*)d_in[16];
    const float* W_f2  = (const float*)d_in[17];
    const float* b_f2  = (const float*)d_in[18];
    const float* W_t1  = (const float*)d_in[19];
    const float* b_t1  = (const float*)d_in[20];
    const float* W_t2  = (const float*)d_in[21];
    const float* b_t2  = (const float*)d_in[22];
    const int*   Lrows = (const int*)d_in[23];
    const int*   Lcols = (const int*)d_in[24];
    float* out = (float*)d_out;

    float *p_x0T, *p_part;
    __nv_bfloat16 *p_x0Th, *p_xth, *p_Winh, *p_Wouth, *p_h2h;
    int *p_cnt, *p_off, *p_wp, *p_bsum;
    int2* p_cpack;
    cudaGetSymbolAddress((void**)&p_x0T,  g_x0T);
    cudaGetSymbolAddress((void**)&p_x0Th, g_x0Th);
    cudaGetSymbolAddress((void**)&p_xth,  g_xth);
    cudaGetSymbolAddress((void**)&p_Winh, g_Winh);
    cudaGetSymbolAddress((void**)&p_Wouth,g_Wouth);
    cudaGetSymbolAddress((void**)&p_part, g_part);
    cudaGetSymbolAddress((void**)&p_h2h,  g_h2h);
    cudaGetSymbolAddress((void**)&p_cnt,  g_cnt);
    cudaGetSymbolAddress((void**)&p_off,  g_off);
    cudaGetSymbolAddress((void**)&p_wp,   g_wp);
    cudaGetSymbolAddress((void**)&p_cpack,g_cpack);
    cudaGetSymbolAddress((void**)&p_bsum, g_bsum);

    // CSR build: 4 wide launches (max thread-level parallelism for scatter)
    hist_kernel<<<(NNZV + 255) / 256, 256>>>(Lrows, p_cnt);
    scan1_kernel<<<64, 256>>>(p_cnt, p_off, p_bsum);
    scan23_kernel<<<1, 1024>>>(p_bsum, p_off, p_wp, out);
    fill_kernel<<<(NNZV + 255) / 256, 256>>>(Lrows, Lcols, Lvals, p_wp, p_cpack);

    // transpose x0 + weight cvt + WvT transpose + bc (one launch)
    transcvt_kernel<<<12545, 256>>>(x0, p_x0T, p_x0Th, W_in, p_Winh, W_out, p_Wouth,
                                    W_qkv + 2 * DM * DM,   // Wv
                                    W_o,
                                    b_qkv + 2 * DM,        // bv
                                    b_o);

    // xt (bf16) = x0T - tc*Lx
    gather_kernel<<<NI, 128>>>(p_x0T, p_x0Th, p_off, p_cpack, t, p_xth);

    // GEMM1 partials (bf16 tensor cores) + We = Wo@Wv (tf32, aliased smem)
    gemm1_we_kernel<<<192, 256>>>(p_xth, p_Winh, p_part, W_o, NI / NSP1);

    // entire middle section in one persistent kernel (folded attention)
    middle_kernel<<<NCTA_MID, 256>>>(t, W_t1, b_t1, W_t2, b_t2, b_in,
                                     g1, be1, W_f1, b_f1, W_f2, b_f2, g2, be2);

    // loss = mean((h2 @ W_out^T + b_out - x0)^2)
    gemm_loss_bf16_kernel<<<dim3(2, NI / 128), 256>>>(p_h2h, p_Wouth, b_out, x0, out);
}

// round 16
// speedup vs baseline: 1.3722x; 1.3178x over previous
#include <cuda_runtime.h>
#include <cuda_bf16.h>
#include <math.h>
#include <stdint.h>

// Problem dims (fixed)
#define BB   256      // batch
#define NI   16384    // n_items
#define DM   512      // d_model
#define DFF  2048     // ff dim
#define NNZV (NI*33)  // 540672
#define NSP1 16       // K-splits for GEMM1
#define NCTA_MID 128  // CTAs in the fused middle kernel

// ---------------- scratch (device globals; no allocation allowed) ----------
__device__ float g_x0T[NI*BB];               // x0 transposed [N,B] fp32
__device__ __nv_bfloat16 g_x0Th[NI*BB];      // x0 transposed [N,B] bf16
__device__ __nv_bfloat16 g_xth[NI*BB];       // x_t [N,B] bf16 (k-major for GEMM1)
__device__ __nv_bfloat16 g_Winh[DM*NI];      // W_in bf16
__device__ __nv_bfloat16 g_Wouth[NI*DM];     // W_out bf16
__device__ float g_part[NSP1*BB*DM];         // split-K partials (reused)
__device__ float g_h  [BB*DM];
__device__ float g_h1 [BB*DM];
__device__ float g_v  [BB*DM];
__device__ float g_at [BB*DM];
__device__ float g_f1 [BB*DFF];
__device__ __nv_bfloat16 g_h2h[BB*DM];       // h2 bf16 (only loss GEMM reads it)
// CSR build scratch
__device__ int   g_cnt[NI];       // zero-initialized; scan1 re-zeros each replay
__device__ int   g_off[NI + 1];
__device__ int   g_wp [NI];
__device__ int2  g_cpack[NNZV];   // packed (col, val_bits)
__device__ int   g_bsum[64];
// grid barrier counters for the fused middle kernel (reset by last CTA)
__device__ int   g_bar[8];

// ---------------- helpers ----------------
__device__ __forceinline__ float tf32r(float x) {
    uint32_t r;
    asm("cvt.rna.tf32.f32 %0, %1;" : "=r"(r) : "f"(x));
    return __uint_as_float(r);
}

__device__ __forceinline__ uint32_t bf2u(__nv_bfloat162 h) {
    uint32_t u;
    memcpy(&u, &h, 4);
    return u;
}

#define MMA_TF32(c, a, b) \
    asm volatile("mma.sync.aligned.m16n8k8.row.col.f32.tf32.tf32.f32 " \
                 "{%0,%1,%2,%3}, {%4,%5,%6,%7}, {%8,%9}, {%0,%1,%2,%3};" \
                 : "+f"((c)[0]), "+f"((c)[1]), "+f"((c)[2]), "+f"((c)[3]) \
                 : "r"((a)[0]), "r"((a)[1]), "r"((a)[2]), "r"((a)[3]), \
                   "r"((b)[0]), "r"((b)[1]))

#define MMA_BF16(c, a, b) \
    asm volatile("mma.sync.aligned.m16n8k16.row.col.f32.bf16.bf16.f32 " \
                 "{%0,%1,%2,%3}, {%4,%5,%6,%7}, {%8,%9}, {%0,%1,%2,%3};" \
                 : "+f"((c)[0]), "+f"((c)[1]), "+f"((c)[2]), "+f"((c)[3]) \
                 : "r"((a)[0]), "r"((a)[1]), "r"((a)[2]), "r"((a)[3]), \
                   "r"((b)[0]), "r"((b)[1]))

#define LDMATRIX_X4_TRANS(r0, r1, r2, r3, addr) \
    asm volatile("ldmatrix.sync.aligned.m8n8.x4.trans.shared.b16 {%0,%1,%2,%3}, [%4];" \
                 : "=r"(r0), "=r"(r1), "=r"(r2), "=r"(r3) : "r"(addr))

__device__ __forceinline__ float gelu_exact(float s) {
    return 0.5f * s * (1.f + erff(s * 0.70710678118654752f));
}

// ---------------- CSR build ----------------
__global__ void hist_kernel(const int* __restrict__ rows, int* __restrict__ cnt) {
    int i = blockIdx.x * blockDim.x + threadIdx.x;
    if (i < NNZV) atomicAdd(&cnt[rows[i]], 1);
}

// per-block (256 bins) exclusive scan, write block totals; resets cnt to 0
__global__ void scan1_kernel(int* __restrict__ cnt, int* __restrict__ off,
                             int* __restrict__ bsum) {
    __shared__ int ws[8];
    int tid = threadIdx.x;
    int i = blockIdx.x * 256 + tid;
    int c = cnt[i];
    cnt[i] = 0;                       // reset for next replay
    int lane = tid & 31, w = tid >> 5;
    int inc = c;
#pragma unroll
    for (int o = 1; o < 32; o <<= 1) {
        int v = __shfl_up_sync(0xffffffffu, inc, o);
        if (lane >= o) inc += v;
    }
    if (lane == 31) ws[w] = inc;
    __syncthreads();
    if (tid < 8) {
        int v = ws[tid];
#pragma unroll
        for (int o = 1; o < 8; o <<= 1) {
            int u = __shfl_up_sync(0xffu, v, o);
            if (tid >= o) v += u;
        }
        ws[tid] = v;
    }
    __syncthreads();
    int base = (w > 0) ? ws[w - 1] : 0;
    off[i] = base + inc - c;
    if (tid == 255) bsum[blockIdx.x] = ws[7];
}

// merged scan2+scan3: scan 64 block sums, apply to off, copy to wp, zero loss
__global__ void scan23_kernel(const int* __restrict__ bsum,
                              int* __restrict__ off, int* __restrict__ wp,
                              float* __restrict__ loss) {
    __shared__ int sb[64];
    __shared__ int ws[2];
    int tid = threadIdx.x;   // 1024
    int lane = tid & 31;
    int v = 0, inc = 0;
    if (tid < 64) {
        v = bsum[tid];
        inc = v;
#pragma unroll
        for (int o = 1; o < 32; o <<= 1) {
            int u = __shfl_up_sync(0xffffffffu, inc, o);
            if (lane >= o) inc += u;
        }
        if (lane == 31) ws[tid >> 5] = inc;
    }
    __syncthreads();
    if (tid < 64) {
        int base = (tid >= 32) ? ws[0] : 0;
        sb[tid] = base + inc - v;
    }
    if (tid == 0) *loss = 0.f;
    __syncthreads();
    if (tid == 0) off[NI] = ws[0] + ws[1];
#pragma unroll
    for (int it = 0; it < 16; it++) {
        int i = it * 1024 + tid;
        int val = off[i] + sb[i >> 8];
        off[i] = val;
        wp[i] = val;
    }
}

__global__ void fill_kernel(const int* __restrict__ rows, const int* __restrict__ cols,
                            const float* __restrict__ vals,
                            int* __restrict__ wp, int2* __restrict__ cpack) {
    int i = blockIdx.x * blockDim.x + threadIdx.x;
    if (i >= NNZV) return;
    int r = rows[i];
    int p = atomicAdd(&wp[r], 1);
    cpack[p] = make_int2(cols[i], __float_as_int(vals[i]));
}

// ------- merged transpose (x0 -> x0T fp32+bf16) + weight fp32->bf16 cvt ----
__global__ void transcvt_kernel(const float* __restrict__ x,
                                float* __restrict__ xt,
                                __nv_bfloat16* __restrict__ xh,
                                const float* __restrict__ wa, __nv_bfloat16* __restrict__ oa,
                                const float* __restrict__ wb, __nv_bfloat16* __restrict__ ob) {
    __shared__ float s[32][33];
    int blk = blockIdx.x, tid = threadIdx.x;
    if (blk < 4096) {
        int n0 = (blk & 511) * 32, b0 = (blk >> 9) * 32;
        int tx = tid & 31, ty = tid >> 5;
#pragma unroll
        for (int i = 0; i < 32; i += 8)
            s[ty + i][tx] = x[(size_t)(b0 + ty + i) * NI + n0 + tx];
        __syncthreads();
#pragma unroll
        for (int i = 0; i < 32; i += 8) {
            float val = s[tx][ty + i];
            size_t idx = (size_t)(n0 + ty + i) * BB + b0 + tx;
            xt[idx] = val;
            xh[idx] = __float2bfloat16(val);
        }
    } else {
        int blk2 = blk - 4096;
        const float* src;
        __nv_bfloat16* dst;
        size_t base;
        if (blk2 < 4096) { src = wa; dst = oa; base = (size_t)blk2 * 2048; }
        else             { src = wb; dst = ob; base = (size_t)(blk2 - 4096) * 2048; }
        size_t i = base + tid * 8;
        float4 v0 = *(const float4*)(src + i);
        float4 v1 = *(const float4*)(src + i + 4);
        uint4 o;
        o.x = bf2u(__floats2bfloat162_rn(v0.x, v0.y));
        o.y = bf2u(__floats2bfloat162_rn(v0.z, v0.w));
        o.z = bf2u(__floats2bfloat162_rn(v1.x, v1.y));
        o.w = bf2u(__floats2bfloat162_rn(v1.z, v1.w));
        *(uint4*)(dst + i) = o;
    }
}

// ---------------- gather: xth[r,:] = bf16(x0T[r,:] - tc[:]*sum val*x0Th[col,:]) --
__global__ void gather_kernel(const float* __restrict__ x0T,
                              const __nv_bfloat16* __restrict__ x0Th,
                              const int* __restrict__ off,
                              const int2* __restrict__ cpack,
                              const float* __restrict__ t,
                              __nv_bfloat16* __restrict__ xth) {
    int r = blockIdx.x;
    int tid = threadIdx.x;        // 0..127
    int b2 = tid * 2;
    int s = off[r], e = off[r + 1];
    float acc0 = 0.f, acc1 = 0.f;
    int j = s;
    for (; j + 3 < e; j += 4) {
        int2 cv0 = __ldg(&cpack[j]),     cv1 = __ldg(&cpack[j + 1]);
        int2 cv2 = __ldg(&cpack[j + 2]), cv3 = __ldg(&cpack[j + 3]);
        float v0 = __int_as_float(cv0.y), v1 = __int_as_float(cv1.y);
        float v2 = __int_as_float(cv2.y), v3 = __int_as_float(cv3.y);
        float2 f0 = __bfloat1622float2(*(const __nv_bfloat162*)(x0Th + (size_t)cv0.x * BB + b2));
        float2 f1 = __bfloat1622float2(*(const __nv_bfloat162*)(x0Th + (size_t)cv1.x * BB + b2));
        float2 f2 = __bfloat1622float2(*(const __nv_bfloat162*)(x0Th + (size_t)cv2.x * BB + b2));
        float2 f3 = __bfloat1622float2(*(const __nv_bfloat162*)(x0Th + (size_t)cv3.x * BB + b2));
        acc0 += v0 * f0.x + v1 * f1.x + v2 * f2.x + v3 * f3.x;
        acc1 += v0 * f0.y + v1 * f1.y + v2 * f2.y + v3 * f3.y;
    }
    for (; j < e; j++) {
        int2 cv0 = __ldg(&cpack[j]);
        float v0 = __int_as_float(cv0.y);
        float2 f0 = __bfloat1622float2(*(const __nv_bfloat162*)(x0Th + (size_t)cv0.x * BB + b2));
        acc0 += v0 * f0.x;
        acc1 += v0 * f0.y;
    }
    float tc0 = 0.5f * t[b2];
    float tc1 = 0.5f * t[b2 + 1];
    float2 xv = *(const float2*)(x0T + (size_t)r * BB + b2);
    __nv_bfloat162 ov = __floats2bfloat162_rn(xv.x - tc0 * acc0, xv.y - tc1 * acc1);
    *(__nv_bfloat162*)(xth + (size_t)r * BB + b2) = ov;
}

// =================== bf16 GEMM1: 128x128 tile, BK=32, double-buffered =======
__global__ __launch_bounds__(256) void gemm1_bf16_kernel(
    const __nv_bfloat16* __restrict__ A,
    const __nv_bfloat16* __restrict__ W,
    float* __restrict__ part, int Kper) {
    __shared__ __nv_bfloat16 As[2][32][136];   // [k][m]
    __shared__ __nv_bfloat16 Ws[2][128][40];   // [n][k]
    int m0 = blockIdx.x * 128;
    int n0 = blockIdx.y * 128;
    int k0 = blockIdx.z * Kper, kend = k0 + Kper;
    int tid = threadIdx.x;
    int w = tid >> 5, lane = tid & 31;
    int wm = (w >> 2) * 64, wn = (w & 3) * 32;
    int g = lane >> 2, tg = lane & 3;
    int lm_k = (lane & 7) + ((lane >> 4) << 3);   // 0..15
    int lm_m = (lane & 8);                        // 0 or 8

    float acc[4][4][4];
#pragma unroll
    for (int i = 0; i < 4; i++)
#pragma unroll
        for (int j = 0; j < 4; j++)
#pragma unroll
            for (int q = 0; q < 4; q++) acc[i][j][q] = 0.f;

    uint4 ra[2], rw[2];
    int a_kk[2], a_mq[2], w_nn, w_kq;
#pragma unroll
    for (int r = 0; r < 2; r++) {
        int idx = tid + 256 * r;
        a_kk[r] = idx >> 4;
        a_mq[r] = (idx & 15) << 3;
    }
    w_nn = tid >> 1;
    w_kq = (tid & 1) << 4;

#define G1_LDG(kt) do { \
    _Pragma("unroll") \
    for (int r = 0; r < 2; r++) \
        ra[r] = *(const uint4*)(A + (size_t)((kt) + a_kk[r]) * BB + m0 + a_mq[r]); \
    rw[0] = *(const uint4*)(W + (size_t)(n0 + w_nn) * NI + (kt) + w_kq); \
    rw[1] = *(const uint4*)(W + (size_t)(n0 + w_nn) * NI + (kt) + w_kq + 8); \
} while (0)

#define G1_STS(buf) do { \
    _Pragma("unroll") \
    for (int r = 0; r < 2; r++) \
        *(uint4*)&As[buf][a_kk[r]][a_mq[r]] = ra[r]; \
    *(uint4*)&Ws[buf][w_nn][w_kq] = rw[0]; \
    *(uint4*)&Ws[buf][w_nn][w_kq + 8] = rw[1]; \
} while (0)

    G1_LDG(k0);
    G1_STS(0);
    __syncthreads();

    int buf = 0;
    for (int kt = k0; kt < kend; kt += 32) {
        bool has_next = (kt + 32 < kend);
        if (has_next) G1_LDG(kt + 32);
#pragma unroll
        for (int kc = 0; kc < 32; kc += 16) {
            uint32_t af[4][4], bfr[4][2];
#pragma unroll
            for (int mi = 0; mi < 4; mi++) {
                uint32_t sa = (uint32_t)__cvta_generic_to_shared(
                    &As[buf][kc + lm_k][wm + mi * 16 + lm_m]);
                LDMATRIX_X4_TRANS(af[mi][0], af[mi][1], af[mi][2], af[mi][3], sa);
            }
#pragma unroll
            for (int ni = 0; ni < 4; ni++) {
                int rn = wn + ni * 8 + g;
                bfr[ni][0] = *(const uint32_t*)&Ws[buf][rn][kc + 2 * tg];
                bfr[ni][1] = *(const uint32_t*)&Ws[buf][rn][kc + 8 + 2 * tg];
            }
#pragma unroll
            for (int mi = 0; mi < 4; mi++)
#pragma unroll
                for (int ni = 0; ni < 4; ni++)
                    MMA_BF16(acc[mi][ni], af[mi], bfr[ni]);
        }
        if (has_next) G1_STS(buf ^ 1);
        __syncthreads();
        buf ^= 1;
    }
#undef G1_LDG
#undef G1_STS

    float* cp = part + (size_t)blockIdx.z * ((size_t)BB * DM);
#pragma unroll
    for (int mi = 0; mi < 4; mi++) {
        int r0 = m0 + wm + mi * 16 + g;
#pragma unroll
        for (int ni = 0; ni < 4; ni++) {
            int col = n0 + wn + ni * 8 + 2 * tg;
            *(float2*)&cp[(size_t)r0 * DM + col] =
                make_float2(acc[mi][ni][0], acc[mi][ni][1]);
            *(float2*)&cp[(size_t)(r0 + 8) * DM + col] =
                make_float2(acc[mi][ni][2], acc[mi][ni][3]);
        }
    }
}

// =========== bf16 loss GEMM: h2h[BB,DM] @ Wouth[NI,DM]^T + bias, MSE ========
__global__ __launch_bounds__(256) void gemm_loss_bf16_kernel(
    const __nv_bfloat16* __restrict__ A,
    const __nv_bfloat16* __restrict__ W,
    const float* __restrict__ bout,
    const float* __restrict__ x0,
    float* __restrict__ out) {
    __shared__ __nv_bfloat16 As[2][128][40];
    __shared__ __nv_bfloat16 Ws[2][128][40];
    __shared__ float sbuf[8];
    int m0 = blockIdx.x * 128;
    int n0 = blockIdx.y * 128;
    int tid = threadIdx.x;
    int w = tid >> 5, lane = tid & 31;
    int wm = (w >> 2) * 64, wn = (w & 3) * 32;
    int g = lane >> 2, tg = lane & 3;

    float acc[4][4][4];
#pragma unroll
    for (int i = 0; i < 4; i++)
#pragma unroll
        for (int j = 0; j < 4; j++)
#pragma unroll
            for (int q = 0; q < 4; q++) acc[i][j][q] = 0.f;

    int mm = tid >> 1;
    int kq = (tid & 1) << 4;
    uint4 ra[2], rw[2];

#define GL_LDG(kt) do { \
    ra[0] = *(const uint4*)(A + (size_t)(m0 + mm) * DM + (kt) + kq); \
    ra[1] = *(const uint4*)(A + (size_t)(m0 + mm) * DM + (kt) + kq + 8); \
    rw[0] = *(const uint4*)(W + (size_t)(n0 + mm) * DM + (kt) + kq); \
    rw[1] = *(const uint4*)(W + (size_t)(n0 + mm) * DM + (kt) + kq + 8); \
} while (0)

#define GL_STS(buf) do { \
    *(uint4*)&As[buf][mm][kq] = ra[0]; \
    *(uint4*)&As[buf][mm][kq + 8] = ra[1]; \
    *(uint4*)&Ws[buf][mm][kq] = rw[0]; \
    *(uint4*)&Ws[buf][mm][kq + 8] = rw[1]; \
} while (0)

    GL_LDG(0);
    GL_STS(0);
    __syncthreads();

    int buf = 0;
    for (int kt = 0; kt < DM; kt += 32) {
        bool has_next = (kt + 32 < DM);
        if (has_next) GL_LDG(kt + 32);
#pragma unroll
        for (int kc = 0; kc < 32; kc += 16) {
            uint32_t af[4][4], bfr[4][2];
#pragma unroll
            for (int mi = 0; mi < 4; mi++) {
                int r0 = wm + mi * 16 + g;
                af[mi][0] = *(const uint32_t*)&As[buf][r0    ][kc + 2 * tg];
                af[mi][1] = *(const uint32_t*)&As[buf][r0 + 8][kc + 2 * tg];
                af[mi][2] = *(const uint32_t*)&As[buf][r0    ][kc + 8 + 2 * tg];
                af[mi][3] = *(const uint32_t*)&As[buf][r0 + 8][kc + 8 + 2 * tg];
            }
#pragma unroll
            for (int ni = 0; ni < 4; ni++) {
                int rn = wn + ni * 8 + g;
                bfr[ni][0] = *(const uint32_t*)&Ws[buf][rn][kc + 2 * tg];
                bfr[ni][1] = *(const uint32_t*)&Ws[buf][rn][kc + 8 + 2 * tg];
            }
#pragma unroll
            for (int mi = 0; mi < 4; mi++)
#pragma unroll
                for (int ni = 0; ni < 4; ni++)
                    MMA_BF16(acc[mi][ni], af[mi], bfr[ni]);
        }
        if (has_next) GL_STS(buf ^ 1);
        __syncthreads();
        buf ^= 1;
    }
#undef GL_LDG
#undef GL_STS

    float local = 0.f;
#pragma unroll
    for (int ni = 0; ni < 4; ni++) {
        int col = n0 + wn + ni * 8 + 2 * tg;
        float bo0 = bout[col], bo1 = bout[col + 1];
#pragma unroll
        for (int mi = 0; mi < 4; mi++) {
            int r0 = m0 + wm + mi * 16 + g;
            float d00 = acc[mi][ni][0] + bo0 - x0[(size_t)r0 * NI + col];
            float d01 = acc[mi][ni][1] + bo1 - x0[(size_t)r0 * NI + col + 1];
            float d10 = acc[mi][ni][2] + bo0 - x0[(size_t)(r0 + 8) * NI + col];
            float d11 = acc[mi][ni][3] + bo1 - x0[(size_t)(r0 + 8) * NI + col + 1];
            local += d00 * d00 + d01 * d01 + d10 * d10 + d11 * d11;
        }
    }
#pragma unroll
    for (int o = 16; o > 0; o >>= 1) local += __shfl_xor_sync(0xffffffffu, local, o);
    if (lane == 0) sbuf[w] = local;
    __syncthreads();
    if (tid == 0) {
        float tot = 0.f;
#pragma unroll
        for (int i = 0; i < 8; i++) tot += sbuf[i];
        atomicAdd(out, tot * (1.f / ((float)BB * (float)NI)));
    }
}

// ================= fused middle section (persistent, grid-barrier) =========
__device__ __forceinline__ void gridbar(int i) {
    __syncthreads();
    if (threadIdx.x == 0) {
        __threadfence();
        atomicAdd(&g_bar[i], 1);
        while (atomicAdd(&g_bar[i], 0) < NCTA_MID) { }
    }
    __syncthreads();
}

// 64x64 TF32 tile GEMM with 256 threads (8 warps, 2m x 4n, warp 32x16).
// act: 0 = +bias, 1 = +bias+gelu, 2 = raw store (partials)
__device__ __noinline__ void tile_gemm64(const float* __restrict__ A,
                                         const float* __restrict__ W,
                                         const float* __restrict__ bias,
                                         float* __restrict__ out,
                                         int N2, int lda, int m0, int n0,
                                         int k0, int kend, int act,
                                         float As[64][20], float Ws[64][20]) {
    int tid = threadIdx.x;
    int w = tid >> 5, lane = tid & 31;
    int wm = (w >> 2) * 32, wn = (w & 3) * 16;
    int g = lane >> 2, tg = lane & 3;
    int mm = tid >> 2, kk = (tid & 3) * 4;

    float acc[2][2][4];
#pragma unroll
    for (int i = 0; i < 2; i++)
#pragma unroll
        for (int j = 0; j < 2; j++)
#pragma unroll
            for (int q = 0; q < 4; q++) acc[i][j][q] = 0.f;

    for (int kt = k0; kt < kend; kt += 16) {
        float4 av = *(const float4*)(A + (size_t)(m0 + mm) * lda + kt + kk);
        As[mm][kk + 0] = tf32r(av.x);
        As[mm][kk + 1] = tf32r(av.y);
        As[mm][kk + 2] = tf32r(av.z);
        As[mm][kk + 3] = tf32r(av.w);
        float4 wv = *(const float4*)(W + (size_t)(n0 + mm) * lda + kt + kk);
        Ws[mm][kk + 0] = tf32r(wv.x);
        Ws[mm][kk + 1] = tf32r(wv.y);
        Ws[mm][kk + 2] = tf32r(wv.z);
        Ws[mm][kk + 3] = tf32r(wv.w);
        __syncthreads();
#pragma unroll
        for (int ks = 0; ks < 16; ks += 8) {
            uint32_t af[2][4], bf[2][2];
#pragma unroll
            for (int mi = 0; mi < 2; mi++) {
                int r0 = wm + mi * 16 + g;
                af[mi][0] = __float_as_uint(As[r0    ][ks + tg]);
                af[mi][1] = __float_as_uint(As[r0 + 8][ks + tg]);
                af[mi][2] = __float_as_uint(As[r0    ][ks + tg + 4]);
                af[mi][3] = __float_as_uint(As[r0 + 8][ks + tg + 4]);
            }
#pragma unroll
            for (int ni = 0; ni < 2; ni++) {
                int rn = wn + ni * 8 + g;
                bf[ni][0] = __float_as_uint(Ws[rn][ks + tg]);
                bf[ni][1] = __float_as_uint(Ws[rn][ks + tg + 4]);
            }
#pragma unroll
            for (int mi = 0; mi < 2; mi++)
#pragma unroll
                for (int ni = 0; ni < 2; ni++)
                    MMA_TF32(acc[mi][ni], af[mi], bf[ni]);
        }
        __syncthreads();
    }
#pragma unroll
    for (int mi = 0; mi < 2; mi++) {
        int r0 = m0 + wm + mi * 16 + g;
#pragma unroll
        for (int ni = 0; ni < 2; ni++) {
            int col = n0 + wn + ni * 8 + 2 * tg;
            float c0 = acc[mi][ni][0], c1 = acc[mi][ni][1];
            float c2 = acc[mi][ni][2], c3 = acc[mi][ni][3];
            if (act < 2) {
                float b0v = bias[col], b1v = bias[col + 1];
                c0 += b0v; c1 += b1v; c2 += b0v; c3 += b1v;
                if (act == 1) {
                    c0 = gelu_exact(c0); c1 = gelu_exact(c1);
                    c2 = gelu_exact(c2); c3 = gelu_exact(c3);
                }
            }
            *(float2*)&out[(size_t)r0 * N2 + col]       = make_float2(c0, c1);
            *(float2*)&out[(size_t)(r0 + 8) * N2 + col] = make_float2(c2, c3);
        }
    }
}

// row layernorm helper: y0/y1 are this thread's 2 elems of a 512-row
__device__ __forceinline__ void ln_row(float y0, float y1,
                                       const float* __restrict__ g,
                                       const float* __restrict__ be,
                                       size_t base, float* sbuf,
                                       float* outf, __nv_bfloat16* outh) {
    int tid = threadIdx.x;
    __syncthreads();
    float s = y0 + y1;
#pragma unroll
    for (int o = 16; o > 0; o >>= 1) s += __shfl_xor_sync(0xffffffffu, s, o);
    if ((tid & 31) == 0) sbuf[tid >> 5] = s;
    __syncthreads();
    if (tid == 0) {
        float tot = 0.f;
        for (int i = 0; i < 8; i++) tot += sbuf[i];
        sbuf[0] = tot;
    }
    __syncthreads();
    float mu = sbuf[0] * (1.f / DM);
    __syncthreads();
    float d0 = y0 - mu, d1 = y1 - mu;
    float q = d0 * d0 + d1 * d1;
#pragma unroll
    for (int o = 16; o > 0; o >>= 1) q += __shfl_xor_sync(0xffffffffu, q, o);
    if ((tid & 31) == 0) sbuf[tid >> 5] = q;
    __syncthreads();
    if (tid == 0) {
        float tot = 0.f;
        for (int i = 0; i < 8; i++) tot += sbuf[i];
        sbuf[0] = tot;
    }
    __syncthreads();
    float inv = rsqrtf(sbuf[0] * (1.f / DM) + 1e-5f);
    float o0 = d0 * inv * g[tid] + be[tid];
    float o1 = d1 * inv * g[tid + 256] + be[tid + 256];
    if (outf) {
        outf[base + tid]       = o0;
        outf[base + tid + 256] = o1;
    } else {
        outh[base + tid]       = __float2bfloat16(o0);
        outh[base + tid + 256] = __float2bfloat16(o1);
    }
}

__global__ __launch_bounds__(256) void middle_kernel(
    const float* __restrict__ t,
    const float* __restrict__ Wt1, const float* __restrict__ bt1,
    const float* __restrict__ Wt2, const float* __restrict__ bt2,
    const float* __restrict__ b_in,
    const float* __restrict__ Wv,  const float* __restrict__ bv,
    const float* __restrict__ Wo,  const float* __restrict__ bo,
    const float* __restrict__ g1,  const float* __restrict__ be1,
    const float* __restrict__ Wf1, const float* __restrict__ bf1,
    const float* __restrict__ Wf2, const float* __restrict__ bf2,
    const float* __restrict__ g2,  const float* __restrict__ be2) {
    __shared__ float As[64][20];
    __shared__ float Ws[64][20];
    __shared__ float sh_u[64];
    __shared__ float sbuf[8];
    int cta = blockIdx.x, tid = threadIdx.x;

    // ---- P0: h = reduce16(part) + b_in + time embedding ----
    {
        int base = cta * 1024;            // 1024 elems per CTA (2 batch rows)
        if (tid < 64) {
            int bb = tid >> 5, j = tid & 31;
            float z = t[cta * 2 + bb] * Wt1[j] + bt1[j];
            sh_u[tid] = z / (1.f + expf(-z));   // silu
        }
        __syncthreads();
#pragma unroll
        for (int k = 0; k < 4; k++) {
            int i = base + k * 256 + tid;
            int d = i & 511;
            int bb = (i >> 9) & 1;
            float s = 0.f;
#pragma unroll
            for (int j = 0; j < NSP1; j++) s += g_part[(size_t)j * (BB * DM) + i];
            s += b_in[d];
            float te = bt2[d];
            const float* wr = Wt2 + d * 32;
#pragma unroll
            for (int j = 0; j < 32; j++) te += sh_u[bb * 32 + j] * wr[j];
            g_h[i] = s + te;
        }
    }
    gridbar(0);

    // ---- PA: v = h @ Wv^T + bv  (32 tiles) ----
    if (cta < 32)
        tile_gemm64(g_h, Wv, bv, g_v, DM, DM,
                    (cta & 3) * 64, (cta >> 2) * 64, 0, DM, 0, As, Ws);
    gridbar(1);

    // ---- PB: at = v @ Wo^T + bo ----
    if (cta < 32)
        tile_gemm64(g_v, Wo, bo, g_at, DM, DM,
                    (cta & 3) * 64, (cta >> 2) * 64, 0, DM, 0, As, Ws);
    gridbar(2);

    // ---- PC: h1 = LN(h + at)  (2 rows per CTA) ----
#pragma unroll
    for (int e = 0; e < 2; e++) {
        int r = cta * 2 + e;
        size_t base = (size_t)r * DM;
        float y0 = g_h[base + tid] + g_at[base + tid];
        float y1 = g_h[base + tid + 256] + g_at[base + tid + 256];
        ln_row(y0, y1, g1, be1, base, sbuf, g_h1, nullptr);
    }
    gridbar(3);

    // ---- PD: f1 = gelu(h1 @ Wf1^T + bf1)  (128 tiles, 1 per CTA) ----
    tile_gemm64(g_h1, Wf1, bf1, g_f1, DFF, DM,
                (cta & 3) * 64, (cta >> 2) * 64, 0, DM, 1, As, Ws);
    gridbar(4);

    // ---- PE: f2 partials = f1 @ Wf2^T (split-4, 128 tiles, 1 per CTA) ----
    {
        int sp = cta >> 5;
        int tile = cta & 31;
        tile_gemm64(g_f1, Wf2, nullptr, g_part + (size_t)sp * (BB * DM), DM, DFF,
                    (tile & 3) * 64, (tile >> 2) * 64, sp * 512, sp * 512 + 512, 2,
                    As, Ws);
    }
    gridbar(5);

    // ---- PF: h2 = LN(h1 + reduce4(part) + bf2) -> bf16  (2 rows per CTA) ----
#pragma unroll
    for (int e = 0; e < 2; e++) {
        int r = cta * 2 + e;
        size_t base = (size_t)r * DM;
        size_t i0 = base + tid, i1 = base + tid + 256;
        float s0 = 0.f, s1 = 0.f;
#pragma unroll
        for (int j = 0; j < 4; j++) {
            s0 += __ldcg(&g_part[(size_t)j * (BB * DM) + i0]);   // stale-L1 safe
            s1 += __ldcg(&g_part[(size_t)j * (BB * DM) + i1]);
        }
        float y0 = __ldcg(&g_h1[i0]) + s0 + bf2[tid];
        float y1 = __ldcg(&g_h1[i1]) + s1 + bf2[tid + 256];
        ln_row(y0, y1, g2, be2, base, sbuf, nullptr, g_h2h);
    }

    // ---- ticket: last CTA resets barrier counters for next graph replay ----
    __syncthreads();
    if (tid == 0) {
        int old = atomicAdd(&g_bar[7], 1);
        if (old == NCTA_MID - 1) {
#pragma unroll
            for (int i = 0; i < 8; i++) atomicExch(&g_bar[i], 0);
        }
    }
}

// ---------------- launch ----------------
extern "C" void kernel_launch(void* const* d_in, const int* in_sizes, int n_in,
                              void* d_out, int out_size) {
    const float* x0    = (const float*)d_in[0];
    const float* t     = (const float*)d_in[1];
    const float* Lvals = (const float*)d_in[2];
    const float* W_in  = (const float*)d_in[3];
    const float* b_in  = (const float*)d_in[4];
    const float* W_out = (const float*)d_in[5];
    const float* b_out = (const float*)d_in[6];
    const float* W_qkv = (const float*)d_in[7];
    const float* b_qkv = (const float*)d_in[8];
    const float* W_o   = (const float*)d_in[9];
    const float* b_o   = (const float*)d_in[10];
    const float* g1    = (const float*)d_in[11];
    const float* be1   = (const float*)d_in[12];
    const float* g2    = (const float*)d_in[13];
    const float* be2   = (const float*)d_in[14];
    const float* W_f1  = (const float*)d_in[15];
    const float* b_f1  = (const float*)d_in[16];
    const float* W_f2  = (const float*)d_in[17];
    const float* b_f2  = (const float*)d_in[18];
    const float* W_t1  = (const float*)d_in[19];
    const float* b_t1  = (const float*)d_in[20];
    const float* W_t2  = (const float*)d_in[21];
    const float* b_t2  = (const float*)d_in[22];
    const int*   Lrows = (const int*)d_in[23];
    const int*   Lcols = (const int*)d_in[24];
    float* out = (float*)d_out;

    float *p_x0T, *p_part;
    __nv_bfloat16 *p_x0Th, *p_xth, *p_Winh, *p_Wouth, *p_h2h;
    int *p_cnt, *p_off, *p_wp, *p_bsum;
    int2* p_cpack;
    cudaGetSymbolAddress((void**)&p_x0T,  g_x0T);
    cudaGetSymbolAddress((void**)&p_x0Th, g_x0Th);
    cudaGetSymbolAddress((void**)&p_xth,  g_xth);
    cudaGetSymbolAddress((void**)&p_Winh, g_Winh);
    cudaGetSymbolAddress((void**)&p_Wouth,g_Wouth);
    cudaGetSymbolAddress((void**)&p_part, g_part);
    cudaGetSymbolAddress((void**)&p_h2h,  g_h2h);
    cudaGetSymbolAddress((void**)&p_cnt,  g_cnt);
    cudaGetSymbolAddress((void**)&p_off,  g_off);
    cudaGetSymbolAddress((void**)&p_wp,   g_wp);
    cudaGetSymbolAddress((void**)&p_cpack,g_cpack);
    cudaGetSymbolAddress((void**)&p_bsum, g_bsum);

    // CSR build: hist -> scan1 (self-resets cnt) -> scan23 (zeroes loss) -> fill
    hist_kernel<<<(NNZV + 255) / 256, 256>>>(Lrows, p_cnt);
    scan1_kernel<<<64, 256>>>(p_cnt, p_off, p_bsum);
    scan23_kernel<<<1, 1024>>>(p_bsum, p_off, p_wp, out);
    fill_kernel<<<(NNZV + 255) / 256, 256>>>(Lrows, Lcols, Lvals, p_wp, p_cpack);

    // transpose + weight cvt (one launch)
    transcvt_kernel<<<12288, 256>>>(x0, p_x0T, p_x0Th, W_in, p_Winh, W_out, p_Wouth);

    // xt (bf16) = x0T - tc*Lx
    gather_kernel<<<NI, 128>>>(p_x0T, p_x0Th, p_off, p_cpack, t, p_xth);

    // GEMM1 partials (bf16 tensor cores)
    gemm1_bf16_kernel<<<dim3(2, 4, NSP1), 256>>>(p_xth, p_Winh, p_part, NI / NSP1);

    // entire middle section in one persistent kernel
    middle_kernel<<<NCTA_MID, 256>>>(t, W_t1, b_t1, W_t2, b_t2, b_in,
                                     W_qkv + 2 * DM * DM, b_qkv + 2 * DM,
                                     W_o, b_o, g1, be1, W_f1, b_f1,
                                     W_f2, b_f2, g2, be2);

    // loss = mean((h2 @ W_out^T + b_out - x0)^2)
    gemm_loss_bf16_kernel<<<dim3(2, NI / 128), 256>>>(p_h2h, p_Wouth, b_out, x0, out);
}

// round 17
// speedup vs baseline: 1.4282x; 1.0409x over previous
#include <cuda_runtime.h>
#include <cuda_bf16.h>
#include <math.h>
#include <stdint.h>

// Problem dims (fixed)
#define BB   256      // batch
#define NI   16384    // n_items
#define DM   512      // d_model
#define DFF  2048     // ff dim
#define NNZV (NI*33)  // 540672
#define NSP1 32       // K-splits for GEMM1
#define NCTA_MID 128  // CTAs in the fused middle kernel

// ---------------- scratch (device globals; no allocation allowed) ----------
__device__ float g_x0T[NI*BB];               // x0 transposed [N,B] fp32
__device__ __nv_bfloat16 g_x0Th[NI*BB];      // x0 transposed [N,B] bf16
__device__ __nv_bfloat16 g_xth[NI*BB];       // x_t [N,B] bf16 (k-major for GEMM1)
__device__ __nv_bfloat16 g_Winh[DM*NI];      // W_in bf16
__device__ __nv_bfloat16 g_Wouth[NI*DM];     // W_out bf16
__device__ float g_part[NSP1*BB*DM];         // split-K partials (reused)
__device__ float g_h  [BB*DM];
__device__ float g_h1 [BB*DM];
__device__ float g_f1 [BB*DFF];
__device__ __nv_bfloat16 g_h2h[BB*DM];       // h2 bf16 (only loss GEMM reads it)
// CSR build scratch
__device__ int   g_cnt[NI];       // zero-initialized; scan1 re-zeros each replay
__device__ int   g_off[NI + 1];
__device__ int   g_wp [NI];
__device__ int2  g_cpack[NNZV];   // packed (col, val_bits)
__device__ int   g_bsum[64];
// grid barrier counters for the fused middle kernel (reset by last CTA)
__device__ int   g_bar[8];

// ---------------- helpers ----------------
__device__ __forceinline__ float tf32r(float x) {
    uint32_t r;
    asm("cvt.rna.tf32.f32 %0, %1;" : "=r"(r) : "f"(x));
    return __uint_as_float(r);
}

__device__ __forceinline__ uint32_t bf2u(__nv_bfloat162 h) {
    uint32_t u;
    memcpy(&u, &h, 4);
    return u;
}

#define MMA_TF32(c, a, b) \
    asm volatile("mma.sync.aligned.m16n8k8.row.col.f32.tf32.tf32.f32 " \
                 "{%0,%1,%2,%3}, {%4,%5,%6,%7}, {%8,%9}, {%0,%1,%2,%3};" \
                 : "+f"((c)[0]), "+f"((c)[1]), "+f"((c)[2]), "+f"((c)[3]) \
                 : "r"((a)[0]), "r"((a)[1]), "r"((a)[2]), "r"((a)[3]), \
                   "r"((b)[0]), "r"((b)[1]))

#define MMA_BF16(c, a, b) \
    asm volatile("mma.sync.aligned.m16n8k16.row.col.f32.bf16.bf16.f32 " \
                 "{%0,%1,%2,%3}, {%4,%5,%6,%7}, {%8,%9}, {%0,%1,%2,%3};" \
                 : "+f"((c)[0]), "+f"((c)[1]), "+f"((c)[2]), "+f"((c)[3]) \
                 : "r"((a)[0]), "r"((a)[1]), "r"((a)[2]), "r"((a)[3]), \
                   "r"((b)[0]), "r"((b)[1]))

#define LDMATRIX_X4_TRANS(r0, r1, r2, r3, addr) \
    asm volatile("ldmatrix.sync.aligned.m8n8.x4.trans.shared.b16 {%0,%1,%2,%3}, [%4];" \
                 : "=r"(r0), "=r"(r1), "=r"(r2), "=r"(r3) : "r"(addr))

__device__ __forceinline__ float gelu_exact(float s) {
    return 0.5f * s * (1.f + erff(s * 0.70710678118654752f));
}

// ---------------- CSR build ----------------
__global__ void hist_kernel(const int* __restrict__ rows, int* __restrict__ cnt) {
    int i = blockIdx.x * blockDim.x + threadIdx.x;
    if (i < NNZV) atomicAdd(&cnt[rows[i]], 1);
}

// per-block (256 bins) exclusive scan, write block totals; resets cnt to 0
__global__ void scan1_kernel(int* __restrict__ cnt, int* __restrict__ off,
                             int* __restrict__ bsum) {
    __shared__ int ws[8];
    int tid = threadIdx.x;
    int i = blockIdx.x * 256 + tid;
    int c = cnt[i];
    cnt[i] = 0;                       // reset for next replay
    int lane = tid & 31, w = tid >> 5;
    int inc = c;
#pragma unroll
    for (int o = 1; o < 32; o <<= 1) {
        int v = __shfl_up_sync(0xffffffffu, inc, o);
        if (lane >= o) inc += v;
    }
    if (lane == 31) ws[w] = inc;
    __syncthreads();
    if (tid < 8) {
        int v = ws[tid];
#pragma unroll
        for (int o = 1; o < 8; o <<= 1) {
            int u = __shfl_up_sync(0xffu, v, o);
            if (tid >= o) v += u;
        }
        ws[tid] = v;
    }
    __syncthreads();
    int base = (w > 0) ? ws[w - 1] : 0;
    off[i] = base + inc - c;
    if (tid == 255) bsum[blockIdx.x] = ws[7];
}

// merged scan2+scan3: scan 64 block sums, apply to off, copy to wp, zero loss
__global__ void scan23_kernel(const int* __restrict__ bsum,
                              int* __restrict__ off, int* __restrict__ wp,
                              float* __restrict__ loss) {
    __shared__ int sb[64];
    __shared__ int ws[2];
    int tid = threadIdx.x;   // 1024
    int lane = tid & 31;
    int v = 0, inc = 0;
    if (tid < 64) {
        v = bsum[tid];
        inc = v;
#pragma unroll
        for (int o = 1; o < 32; o <<= 1) {
            int u = __shfl_up_sync(0xffffffffu, inc, o);
            if (lane >= o) inc += u;
        }
        if (lane == 31) ws[tid >> 5] = inc;
    }
    __syncthreads();
    if (tid < 64) {
        int base = (tid >= 32) ? ws[0] : 0;
        sb[tid] = base + inc - v;
    }
    if (tid == 0) *loss = 0.f;
    __syncthreads();
    if (tid == 0) off[NI] = ws[0] + ws[1];
#pragma unroll
    for (int it = 0; it < 16; it++) {
        int i = it * 1024 + tid;
        int val = off[i] + sb[i >> 8];
        off[i] = val;
        wp[i] = val;
    }
}

__global__ void fill_kernel(const int* __restrict__ rows, const int* __restrict__ cols,
                            const float* __restrict__ vals,
                            int* __restrict__ wp, int2* __restrict__ cpack) {
    int i = blockIdx.x * blockDim.x + threadIdx.x;
    if (i >= NNZV) return;
    int r = rows[i];
    int p = atomicAdd(&wp[r], 1);
    cpack[p] = make_int2(cols[i], __float_as_int(vals[i]));
}

// ------- merged transpose (x0 -> x0T fp32+bf16) + weight fp32->bf16 cvt ----
__global__ void transcvt_kernel(const float* __restrict__ x,
                                float* __restrict__ xt,
                                __nv_bfloat16* __restrict__ xh,
                                const float* __restrict__ wa, __nv_bfloat16* __restrict__ oa,
                                const float* __restrict__ wb, __nv_bfloat16* __restrict__ ob) {
    __shared__ float s[32][33];
    int blk = blockIdx.x, tid = threadIdx.x;
    if (blk < 4096) {
        int n0 = (blk & 511) * 32, b0 = (blk >> 9) * 32;
        int tx = tid & 31, ty = tid >> 5;
#pragma unroll
        for (int i = 0; i < 32; i += 8)
            s[ty + i][tx] = x[(size_t)(b0 + ty + i) * NI + n0 + tx];
        __syncthreads();
#pragma unroll
        for (int i = 0; i < 32; i += 8) {
            float val = s[tx][ty + i];
            size_t idx = (size_t)(n0 + ty + i) * BB + b0 + tx;
            xt[idx] = val;
            xh[idx] = __float2bfloat16(val);
        }
    } else {
        int blk2 = blk - 4096;
        const float* src;
        __nv_bfloat16* dst;
        size_t base;
        if (blk2 < 4096) { src = wa; dst = oa; base = (size_t)blk2 * 2048; }
        else             { src = wb; dst = ob; base = (size_t)(blk2 - 4096) * 2048; }
        size_t i = base + tid * 8;
        float4 v0 = *(const float4*)(src + i);
        float4 v1 = *(const float4*)(src + i + 4);
        uint4 o;
        o.x = bf2u(__floats2bfloat162_rn(v0.x, v0.y));
        o.y = bf2u(__floats2bfloat162_rn(v0.z, v0.w));
        o.z = bf2u(__floats2bfloat162_rn(v1.x, v1.y));
        o.w = bf2u(__floats2bfloat162_rn(v1.z, v1.w));
        *(uint4*)(dst + i) = o;
    }
}

// ---------------- gather: xth[r,:] = bf16(x0T[r,:] - tc[:]*sum val*x0Th[col,:]) --
__global__ void gather_kernel(const float* __restrict__ x0T,
                              const __nv_bfloat16* __restrict__ x0Th,
                              const int* __restrict__ off,
                              const int2* __restrict__ cpack,
                              const float* __restrict__ t,
                              __nv_bfloat16* __restrict__ xth) {
    int r = blockIdx.x;
    int tid = threadIdx.x;        // 0..127
    int b2 = tid * 2;
    int s = off[r], e = off[r + 1];
    float acc0 = 0.f, acc1 = 0.f;
    int j = s;
    for (; j + 3 < e; j += 4) {
        int2 cv0 = __ldg(&cpack[j]),     cv1 = __ldg(&cpack[j + 1]);
        int2 cv2 = __ldg(&cpack[j + 2]), cv3 = __ldg(&cpack[j + 3]);
        float v0 = __int_as_float(cv0.y), v1 = __int_as_float(cv1.y);
        float v2 = __int_as_float(cv2.y), v3 = __int_as_float(cv3.y);
        float2 f0 = __bfloat1622float2(*(const __nv_bfloat162*)(x0Th + (size_t)cv0.x * BB + b2));
        float2 f1 = __bfloat1622float2(*(const __nv_bfloat162*)(x0Th + (size_t)cv1.x * BB + b2));
        float2 f2 = __bfloat1622float2(*(const __nv_bfloat162*)(x0Th + (size_t)cv2.x * BB + b2));
        float2 f3 = __bfloat1622float2(*(const __nv_bfloat162*)(x0Th + (size_t)cv3.x * BB + b2));
        acc0 += v0 * f0.x + v1 * f1.x + v2 * f2.x + v3 * f3.x;
        acc1 += v0 * f0.y + v1 * f1.y + v2 * f2.y + v3 * f3.y;
    }
    for (; j < e; j++) {
        int2 cv0 = __ldg(&cpack[j]);
        float v0 = __int_as_float(cv0.y);
        float2 f0 = __bfloat1622float2(*(const __nv_bfloat162*)(x0Th + (size_t)cv0.x * BB + b2));
        acc0 += v0 * f0.x;
        acc1 += v0 * f0.y;
    }
    float tc0 = 0.5f * t[b2];
    float tc1 = 0.5f * t[b2 + 1];
    float2 xv = *(const float2*)(x0T + (size_t)r * BB + b2);
    __nv_bfloat162 ov = __floats2bfloat162_rn(xv.x - tc0 * acc0, xv.y - tc1 * acc1);
    *(__nv_bfloat162*)(xth + (size_t)r * BB + b2) = ov;
}

// =================== bf16 GEMM1: 128x128 tile, BK=32, double-buffered =======
__global__ __launch_bounds__(256) void gemm1_bf16_kernel(
    const __nv_bfloat16* __restrict__ A,
    const __nv_bfloat16* __restrict__ W,
    float* __restrict__ part, int Kper) {
    __shared__ __nv_bfloat16 As[2][32][136];   // [k][m]
    __shared__ __nv_bfloat16 Ws[2][128][40];   // [n][k]
    int m0 = blockIdx.x * 128;
    int n0 = blockIdx.y * 128;
    int k0 = blockIdx.z * Kper, kend = k0 + Kper;
    int tid = threadIdx.x;
    int w = tid >> 5, lane = tid & 31;
    int wm = (w >> 2) * 64, wn = (w & 3) * 32;
    int g = lane >> 2, tg = lane & 3;
    int lm_k = (lane & 7) + ((lane >> 4) << 3);   // 0..15
    int lm_m = (lane & 8);                        // 0 or 8

    float acc[4][4][4];
#pragma unroll
    for (int i = 0; i < 4; i++)
#pragma unroll
        for (int j = 0; j < 4; j++)
#pragma unroll
            for (int q = 0; q < 4; q++) acc[i][j][q] = 0.f;

    uint4 ra[2], rw[2];
    int a_kk[2], a_mq[2], w_nn, w_kq;
#pragma unroll
    for (int r = 0; r < 2; r++) {
        int idx = tid + 256 * r;
        a_kk[r] = idx >> 4;
        a_mq[r] = (idx & 15) << 3;
    }
    w_nn = tid >> 1;
    w_kq = (tid & 1) << 4;

#define G1_LDG(kt) do { \
    _Pragma("unroll") \
    for (int r = 0; r < 2; r++) \
        ra[r] = *(const uint4*)(A + (size_t)((kt) + a_kk[r]) * BB + m0 + a_mq[r]); \
    rw[0] = *(const uint4*)(W + (size_t)(n0 + w_nn) * NI + (kt) + w_kq); \
    rw[1] = *(const uint4*)(W + (size_t)(n0 + w_nn) * NI + (kt) + w_kq + 8); \
} while (0)

#define G1_STS(buf) do { \
    _Pragma("unroll") \
    for (int r = 0; r < 2; r++) \
        *(uint4*)&As[buf][a_kk[r]][a_mq[r]] = ra[r]; \
    *(uint4*)&Ws[buf][w_nn][w_kq] = rw[0]; \
    *(uint4*)&Ws[buf][w_nn][w_kq + 8] = rw[1]; \
} while (0)

    G1_LDG(k0);
    G1_STS(0);
    __syncthreads();

    int buf = 0;
    for (int kt = k0; kt < kend; kt += 32) {
        bool has_next = (kt + 32 < kend);
        if (has_next) G1_LDG(kt + 32);
#pragma unroll
        for (int kc = 0; kc < 32; kc += 16) {
            uint32_t af[4][4], bfr[4][2];
#pragma unroll
            for (int mi = 0; mi < 4; mi++) {
                uint32_t sa = (uint32_t)__cvta_generic_to_shared(
                    &As[buf][kc + lm_k][wm + mi * 16 + lm_m]);
                LDMATRIX_X4_TRANS(af[mi][0], af[mi][1], af[mi][2], af[mi][3], sa);
            }
#pragma unroll
            for (int ni = 0; ni < 4; ni++) {
                int rn = wn + ni * 8 + g;
                bfr[ni][0] = *(const uint32_t*)&Ws[buf][rn][kc + 2 * tg];
                bfr[ni][1] = *(const uint32_t*)&Ws[buf][rn][kc + 8 + 2 * tg];
            }
#pragma unroll
            for (int mi = 0; mi < 4; mi++)
#pragma unroll
                for (int ni = 0; ni < 4; ni++)
                    MMA_BF16(acc[mi][ni], af[mi], bfr[ni]);
        }
        if (has_next) G1_STS(buf ^ 1);
        __syncthreads();
        buf ^= 1;
    }
#undef G1_LDG
#undef G1_STS

    float* cp = part + (size_t)blockIdx.z * ((size_t)BB * DM);
#pragma unroll
    for (int mi = 0; mi < 4; mi++) {
        int r0 = m0 + wm + mi * 16 + g;
#pragma unroll
        for (int ni = 0; ni < 4; ni++) {
            int col = n0 + wn + ni * 8 + 2 * tg;
            *(float2*)&cp[(size_t)r0 * DM + col] =
                make_float2(acc[mi][ni][0], acc[mi][ni][1]);
            *(float2*)&cp[(size_t)(r0 + 8) * DM + col] =
                make_float2(acc[mi][ni][2], acc[mi][ni][3]);
        }
    }
}

// =========== bf16 loss GEMM: h2h[BB,DM] @ Wouth[NI,DM]^T + bias, MSE ========
__global__ __launch_bounds__(256) void gemm_loss_bf16_kernel(
    const __nv_bfloat16* __restrict__ A,
    const __nv_bfloat16* __restrict__ W,
    const float* __restrict__ bout,
    const float* __restrict__ x0,
    float* __restrict__ out) {
    __shared__ __nv_bfloat16 As[2][128][40];
    __shared__ __nv_bfloat16 Ws[2][128][40];
    __shared__ float sbuf[8];
    int m0 = blockIdx.x * 128;
    int n0 = blockIdx.y * 128;
    int tid = threadIdx.x;
    int w = tid >> 5, lane = tid & 31;
    int wm = (w >> 2) * 64, wn = (w & 3) * 32;
    int g = lane >> 2, tg = lane & 3;

    float acc[4][4][4];
#pragma unroll
    for (int i = 0; i < 4; i++)
#pragma unroll
        for (int j = 0; j < 4; j++)
#pragma unroll
            for (int q = 0; q < 4; q++) acc[i][j][q] = 0.f;

    int mm = tid >> 1;
    int kq = (tid & 1) << 4;
    uint4 ra[2], rw[2];

#define GL_LDG(kt) do { \
    ra[0] = *(const uint4*)(A + (size_t)(m0 + mm) * DM + (kt) + kq); \
    ra[1] = *(const uint4*)(A + (size_t)(m0 + mm) * DM + (kt) + kq + 8); \
    rw[0] = *(const uint4*)(W + (size_t)(n0 + mm) * DM + (kt) + kq); \
    rw[1] = *(const uint4*)(W + (size_t)(n0 + mm) * DM + (kt) + kq + 8); \
} while (0)

#define GL_STS(buf) do { \
    *(uint4*)&As[buf][mm][kq] = ra[0]; \
    *(uint4*)&As[buf][mm][kq + 8] = ra[1]; \
    *(uint4*)&Ws[buf][mm][kq] = rw[0]; \
    *(uint4*)&Ws[buf][mm][kq + 8] = rw[1]; \
} while (0)

    GL_LDG(0);
    GL_STS(0);
    __syncthreads();

    int buf = 0;
    for (int kt = 0; kt < DM; kt += 32) {
        bool has_next = (kt + 32 < DM);
        if (has_next) GL_LDG(kt + 32);
#pragma unroll
        for (int kc = 0; kc < 32; kc += 16) {
            uint32_t af[4][4], bfr[4][2];
#pragma unroll
            for (int mi = 0; mi < 4; mi++) {
                int r0 = wm + mi * 16 + g;
                af[mi][0] = *(const uint32_t*)&As[buf][r0    ][kc + 2 * tg];
                af[mi][1] = *(const uint32_t*)&As[buf][r0 + 8][kc + 2 * tg];
                af[mi][2] = *(const uint32_t*)&As[buf][r0    ][kc + 8 + 2 * tg];
                af[mi][3] = *(const uint32_t*)&As[buf][r0 + 8][kc + 8 + 2 * tg];
            }
#pragma unroll
            for (int ni = 0; ni < 4; ni++) {
                int rn = wn + ni * 8 + g;
                bfr[ni][0] = *(const uint32_t*)&Ws[buf][rn][kc + 2 * tg];
                bfr[ni][1] = *(const uint32_t*)&Ws[buf][rn][kc + 8 + 2 * tg];
            }
#pragma unroll
            for (int mi = 0; mi < 4; mi++)
#pragma unroll
                for (int ni = 0; ni < 4; ni++)
                    MMA_BF16(acc[mi][ni], af[mi], bfr[ni]);
        }
        if (has_next) GL_STS(buf ^ 1);
        __syncthreads();
        buf ^= 1;
    }
#undef GL_LDG
#undef GL_STS

    float local = 0.f;
#pragma unroll
    for (int ni = 0; ni < 4; ni++) {
        int col = n0 + wn + ni * 8 + 2 * tg;
        float bo0 = bout[col], bo1 = bout[col + 1];
#pragma unroll
        for (int mi = 0; mi < 4; mi++) {
            int r0 = m0 + wm + mi * 16 + g;
            float d00 = acc[mi][ni][0] + bo0 - x0[(size_t)r0 * NI + col];
            float d01 = acc[mi][ni][1] + bo1 - x0[(size_t)r0 * NI + col + 1];
            float d10 = acc[mi][ni][2] + bo0 - x0[(size_t)(r0 + 8) * NI + col];
            float d11 = acc[mi][ni][3] + bo1 - x0[(size_t)(r0 + 8) * NI + col + 1];
            local += d00 * d00 + d01 * d01 + d10 * d10 + d11 * d11;
        }
    }
#pragma unroll
    for (int o = 16; o > 0; o >>= 1) local += __shfl_xor_sync(0xffffffffu, local, o);
    if (lane == 0) sbuf[w] = local;
    __syncthreads();
    if (tid == 0) {
        float tot = 0.f;
#pragma unroll
        for (int i = 0; i < 8; i++) tot += sbuf[i];
        atomicAdd(out, tot * (1.f / ((float)BB * (float)NI)));
    }
}

// ================= fused middle section (persistent, grid-barrier) =========
__device__ __forceinline__ void gridbar(int i) {
    __syncthreads();
    if (threadIdx.x == 0) {
        __threadfence();
        atomicAdd(&g_bar[i], 1);
        while (atomicAdd(&g_bar[i], 0) < NCTA_MID) { }
    }
    __syncthreads();
}

// 64x64 TF32 tile GEMM with 256 threads (8 warps, 2m x 4n, warp 32x16).
// act: 0 = +bias, 1 = +bias+gelu, 2 = raw store (partials)
__device__ __noinline__ void tile_gemm64(const float* __restrict__ A,
                                         const float* __restrict__ W,
                                         const float* __restrict__ bias,
                                         float* __restrict__ out,
                                         int N2, int lda, int m0, int n0,
                                         int k0, int kend, int act,
                                         float As[64][20], float Ws[64][20]) {
    int tid = threadIdx.x;
    int w = tid >> 5, lane = tid & 31;
    int wm = (w >> 2) * 32, wn = (w & 3) * 16;
    int g = lane >> 2, tg = lane & 3;
    int mm = tid >> 2, kk = (tid & 3) * 4;

    float acc[2][2][4];
#pragma unroll
    for (int i = 0; i < 2; i++)
#pragma unroll
        for (int j = 0; j < 2; j++)
#pragma unroll
            for (int q = 0; q < 4; q++) acc[i][j][q] = 0.f;

    for (int kt = k0; kt < kend; kt += 16) {
        float4 av = *(const float4*)(A + (size_t)(m0 + mm) * lda + kt + kk);
        As[mm][kk + 0] = tf32r(av.x);
        As[mm][kk + 1] = tf32r(av.y);
        As[mm][kk + 2] = tf32r(av.z);
        As[mm][kk + 3] = tf32r(av.w);
        float4 wv = *(const float4*)(W + (size_t)(n0 + mm) * lda + kt + kk);
        Ws[mm][kk + 0] = tf32r(wv.x);
        Ws[mm][kk + 1] = tf32r(wv.y);
        Ws[mm][kk + 2] = tf32r(wv.z);
        Ws[mm][kk + 3] = tf32r(wv.w);
        __syncthreads();
#pragma unroll
        for (int ks = 0; ks < 16; ks += 8) {
            uint32_t af[2][4], bf[2][2];
#pragma unroll
            for (int mi = 0; mi < 2; mi++) {
                int r0 = wm + mi * 16 + g;
                af[mi][0] = __float_as_uint(As[r0    ][ks + tg]);
                af[mi][1] = __float_as_uint(As[r0 + 8][ks + tg]);
                af[mi][2] = __float_as_uint(As[r0    ][ks + tg + 4]);
                af[mi][3] = __float_as_uint(As[r0 + 8][ks + tg + 4]);
            }
#pragma unroll
            for (int ni = 0; ni < 2; ni++) {
                int rn = wn + ni * 8 + g;
                bf[ni][0] = __float_as_uint(Ws[rn][ks + tg]);
                bf[ni][1] = __float_as_uint(Ws[rn][ks + tg + 4]);
            }
#pragma unroll
            for (int mi = 0; mi < 2; mi++)
#pragma unroll
                for (int ni = 0; ni < 2; ni++)
                    MMA_TF32(acc[mi][ni], af[mi], bf[ni]);
        }
        __syncthreads();
    }
#pragma unroll
    for (int mi = 0; mi < 2; mi++) {
        int r0 = m0 + wm + mi * 16 + g;
#pragma unroll
        for (int ni = 0; ni < 2; ni++) {
            int col = n0 + wn + ni * 8 + 2 * tg;
            float c0 = acc[mi][ni][0], c1 = acc[mi][ni][1];
            float c2 = acc[mi][ni][2], c3 = acc[mi][ni][3];
            if (act < 2) {
                float b0v = bias[col], b1v = bias[col + 1];
                c0 += b0v; c1 += b1v; c2 += b0v; c3 += b1v;
                if (act == 1) {
                    c0 = gelu_exact(c0); c1 = gelu_exact(c1);
                    c2 = gelu_exact(c2); c3 = gelu_exact(c3);
                }
            }
            *(float2*)&out[(size_t)r0 * N2 + col]       = make_float2(c0, c1);
            *(float2*)&out[(size_t)(r0 + 8) * N2 + col] = make_float2(c2, c3);
        }
    }
}

// PB variant: A = reduce4(g_part[0..4)) + bv  (ldcg; addrs were read in P0),
// W = Wo, raw partial output. 64x64 tile.
__device__ __noinline__ void tile_gemm64_vred(const float* __restrict__ W,
                                              const float* __restrict__ bv,
                                              float* __restrict__ out,
                                              int m0, int n0, int k0, int kend,
                                              float As[64][20], float Ws[64][20]) {
    int tid = threadIdx.x;
    int w = tid >> 5, lane = tid & 31;
    int wm = (w >> 2) * 32, wn = (w & 3) * 16;
    int g = lane >> 2, tg = lane & 3;
    int mm = tid >> 2, kk = (tid & 3) * 4;

    float acc[2][2][4];
#pragma unroll
    for (int i = 0; i < 2; i++)
#pragma unroll
        for (int j = 0; j < 2; j++)
#pragma unroll
            for (int q = 0; q < 4; q++) acc[i][j][q] = 0.f;

    for (int kt = k0; kt < kend; kt += 16) {
        float4 bvv = *(const float4*)(bv + kt + kk);
        float4 av = make_float4(bvv.x, bvv.y, bvv.z, bvv.w);
#pragma unroll
        for (int j = 0; j < 4; j++) {
            float4 p = __ldcg((const float4*)(g_part + (size_t)j * (BB * DM) +
                                              (size_t)(m0 + mm) * DM + kt + kk));
            av.x += p.x; av.y += p.y; av.z += p.z; av.w += p.w;
        }
        As[mm][kk + 0] = tf32r(av.x);
        As[mm][kk + 1] = tf32r(av.y);
        As[mm][kk + 2] = tf32r(av.z);
        As[mm][kk + 3] = tf32r(av.w);
        float4 wv = *(const float4*)(W + (size_t)(n0 + mm) * DM + kt + kk);
        Ws[mm][kk + 0] = tf32r(wv.x);
        Ws[mm][kk + 1] = tf32r(wv.y);
        Ws[mm][kk + 2] = tf32r(wv.z);
        Ws[mm][kk + 3] = tf32r(wv.w);
        __syncthreads();
#pragma unroll
        for (int ks = 0; ks < 16; ks += 8) {
            uint32_t af[2][4], bf[2][2];
#pragma unroll
            for (int mi = 0; mi < 2; mi++) {
                int r0 = wm + mi * 16 + g;
                af[mi][0] = __float_as_uint(As[r0    ][ks + tg]);
                af[mi][1] = __float_as_uint(As[r0 + 8][ks + tg]);
                af[mi][2] = __float_as_uint(As[r0    ][ks + tg + 4]);
                af[mi][3] = __float_as_uint(As[r0 + 8][ks + tg + 4]);
            }
#pragma unroll
            for (int ni = 0; ni < 2; ni++) {
                int rn = wn + ni * 8 + g;
                bf[ni][0] = __float_as_uint(Ws[rn][ks + tg]);
                bf[ni][1] = __float_as_uint(Ws[rn][ks + tg + 4]);
            }
#pragma unroll
            for (int mi = 0; mi < 2; mi++)
#pragma unroll
                for (int ni = 0; ni < 2; ni++)
                    MMA_TF32(acc[mi][ni], af[mi], bf[ni]);
        }
        __syncthreads();
    }
#pragma unroll
    for (int mi = 0; mi < 2; mi++) {
        int r0 = m0 + wm + mi * 16 + g;
#pragma unroll
        for (int ni = 0; ni < 2; ni++) {
            int col = n0 + wn + ni * 8 + 2 * tg;
            *(float2*)&out[(size_t)r0 * DM + col] =
                make_float2(acc[mi][ni][0], acc[mi][ni][1]);
            *(float2*)&out[(size_t)(r0 + 8) * DM + col] =
                make_float2(acc[mi][ni][2], acc[mi][ni][3]);
        }
    }
}

// row layernorm helper: y0/y1 are this thread's 2 elems of a 512-row
__device__ __forceinline__ void ln_row(float y0, float y1,
                                       const float* __restrict__ g,
                                       const float* __restrict__ be,
                                       size_t base, float* sbuf,
                                       float* outf, __nv_bfloat16* outh) {
    int tid = threadIdx.x;
    __syncthreads();
    float s = y0 + y1;
#pragma unroll
    for (int o = 16; o > 0; o >>= 1) s += __shfl_xor_sync(0xffffffffu, s, o);
    if ((tid & 31) == 0) sbuf[tid >> 5] = s;
    __syncthreads();
    if (tid == 0) {
        float tot = 0.f;
        for (int i = 0; i < 8; i++) tot += sbuf[i];
        sbuf[0] = tot;
    }
    __syncthreads();
    float mu = sbuf[0] * (1.f / DM);
    __syncthreads();
    float d0 = y0 - mu, d1 = y1 - mu;
    float q = d0 * d0 + d1 * d1;
#pragma unroll
    for (int o = 16; o > 0; o >>= 1) q += __shfl_xor_sync(0xffffffffu, q, o);
    if ((tid & 31) == 0) sbuf[tid >> 5] = q;
    __syncthreads();
    if (tid == 0) {
        float tot = 0.f;
        for (int i = 0; i < 8; i++) tot += sbuf[i];
        sbuf[0] = tot;
    }
    __syncthreads();
    float inv = rsqrtf(sbuf[0] * (1.f / DM) + 1e-5f);
    float o0 = d0 * inv * g[tid] + be[tid];
    float o1 = d1 * inv * g[tid + 256] + be[tid + 256];
    if (outf) {
        outf[base + tid]       = o0;
        outf[base + tid + 256] = o1;
    } else {
        outh[base + tid]       = __float2bfloat16(o0);
        outh[base + tid + 256] = __float2bfloat16(o1);
    }
}

__global__ __launch_bounds__(256) void middle_kernel(
    const float* __restrict__ t,
    const float* __restrict__ Wt1, const float* __restrict__ bt1,
    const float* __restrict__ Wt2, const float* __restrict__ bt2,
    const float* __restrict__ b_in,
    const float* __restrict__ Wv,  const float* __restrict__ bv,
    const float* __restrict__ Wo,  const float* __restrict__ bo,
    const float* __restrict__ g1,  const float* __restrict__ be1,
    const float* __restrict__ Wf1, const float* __restrict__ bf1,
    const float* __restrict__ Wf2, const float* __restrict__ bf2,
    const float* __restrict__ g2,  const float* __restrict__ be2) {
    __shared__ float As[64][20];
    __shared__ float Ws[64][20];
    __shared__ float sh_u[64];
    __shared__ float sbuf[8];
    int cta = blockIdx.x, tid = threadIdx.x;

    // ---- P0: h = reduce32(part) + b_in + time embedding ----
    {
        int base = cta * 1024;            // 1024 elems per CTA (2 batch rows)
        if (tid < 64) {
            int bb = tid >> 5, j = tid & 31;
            float z = t[cta * 2 + bb] * Wt1[j] + bt1[j];
            sh_u[tid] = z / (1.f + expf(-z));   // silu
        }
        __syncthreads();
#pragma unroll
        for (int k = 0; k < 4; k++) {
            int i = base + k * 256 + tid;
            int d = i & 511;
            int bb = (i >> 9) & 1;
            float s = 0.f;
#pragma unroll
            for (int j = 0; j < NSP1; j++) s += g_part[(size_t)j * (BB * DM) + i];
            s += b_in[d];
            float te = bt2[d];
            const float* wr = Wt2 + d * 32;
#pragma unroll
            for (int j = 0; j < 32; j++) te += sh_u[bb * 32 + j] * wr[j];
            g_h[i] = s + te;
        }
    }
    gridbar(0);

    // ---- PA: v partials = h @ Wv^T (split-K4, all 128 CTAs, slots 0-3) ----
    {
        int sp = cta >> 5;
        int tile = cta & 31;
        tile_gemm64(g_h, Wv, nullptr, g_part + (size_t)sp * (BB * DM), DM, DM,
                    (tile & 3) * 64, (tile >> 2) * 64, sp * 128, sp * 128 + 128, 2,
                    As, Ws);
    }
    gridbar(1);

    // ---- PB: at partials = (reduce4(v)+bv) @ Wo^T (split-K4, slots 4-7) ----
    {
        int sp = cta >> 5;
        int tile = cta & 31;
        tile_gemm64_vred(Wo, bv, g_part + (size_t)(4 + sp) * (BB * DM),
                         (tile & 3) * 64, (tile >> 2) * 64,
                         sp * 128, sp * 128 + 128, As, Ws);
    }
    gridbar(2);

    // ---- PC: h1 = LN(h + reduce4(at) + bo)  (2 rows per CTA) ----
#pragma unroll
    for (int e = 0; e < 2; e++) {
        int r = cta * 2 + e;
        size_t base = (size_t)r * DM;
        size_t i0 = base + tid, i1 = base + tid + 256;
        float a0 = 0.f, a1 = 0.f;
#pragma unroll
        for (int j = 4; j < 8; j++) {
            a0 += __ldcg(&g_part[(size_t)j * (BB * DM) + i0]);   // P0 read; PB rewrote
            a1 += __ldcg(&g_part[(size_t)j * (BB * DM) + i1]);
        }
        float y0 = g_h[i0] + a0 + bo[tid];
        float y1 = g_h[i1] + a1 + bo[tid + 256];
        ln_row(y0, y1, g1, be1, base, sbuf, g_h1, nullptr);
    }
    gridbar(3);

    // ---- PD: f1 = gelu(h1 @ Wf1^T + bf1)  (128 tiles, 1 per CTA) ----
    tile_gemm64(g_h1, Wf1, bf1, g_f1, DFF, DM,
                (cta & 3) * 64, (cta >> 2) * 64, 0, DM, 1, As, Ws);
    gridbar(4);

    // ---- PE: f2 partials = f1 @ Wf2^T (split-4, slots 0-3) ----
    {
        int sp = cta >> 5;
        int tile = cta & 31;
        tile_gemm64(g_f1, Wf2, nullptr, g_part + (size_t)sp * (BB * DM), DM, DFF,
                    (tile & 3) * 64, (tile >> 2) * 64, sp * 512, sp * 512 + 512, 2,
                    As, Ws);
    }
    gridbar(5);

    // ---- PF: h2 = LN(h1 + reduce4(part) + bf2) -> bf16  (2 rows per CTA) ----
#pragma unroll
    for (int e = 0; e < 2; e++) {
        int r = cta * 2 + e;
        size_t base = (size_t)r * DM;
        size_t i0 = base + tid, i1 = base + tid + 256;
        float s0 = 0.f, s1 = 0.f;
#pragma unroll
        for (int j = 0; j < 4; j++) {
            s0 += __ldcg(&g_part[(size_t)j * (BB * DM) + i0]);   // stale-L1 safe
            s1 += __ldcg(&g_part[(size_t)j * (BB * DM) + i1]);
        }
        float y0 = __ldcg(&g_h1[i0]) + s0 + bf2[tid];
        float y1 = __ldcg(&g_h1[i1]) + s1 + bf2[tid + 256];
        ln_row(y0, y1, g2, be2, base, sbuf, nullptr, g_h2h);
    }

    // ---- ticket: last CTA resets barrier counters for next graph replay ----
    __syncthreads();
    if (tid == 0) {
        int old = atomicAdd(&g_bar[7], 1);
        if (old == NCTA_MID - 1) {
#pragma unroll
            for (int i = 0; i < 8; i++) atomicExch(&g_bar[i], 0);
        }
    }
}

// ---------------- launch ----------------
extern "C" void kernel_launch(void* const* d_in, const int* in_sizes, int n_in,
                              void* d_out, int out_size) {
    const float* x0    = (const float*)d_in[0];
    const float* t     = (const float*)d_in[1];
    const float* Lvals = (const float*)d_in[2];
    const float* W_in  = (const float*)d_in[3];
    const float* b_in  = (const float*)d_in[4];
    const float* W_out = (const float*)d_in[5];
    const float* b_out = (const float*)d_in[6];
    const float* W_qkv = (const float*)d_in[7];
    const float* b_qkv = (const float*)d_in[8];
    const float* W_o   = (const float*)d_in[9];
    const float* b_o   = (const float*)d_in[10];
    const float* g1    = (const float*)d_in[11];
    const float* be1   = (const float*)d_in[12];
    const float* g2    = (const float*)d_in[13];
    const float* be2   = (const float*)d_in[14];
    const float* W_f1  = (const float*)d_in[15];
    const float* b_f1  = (const float*)d_in[16];
    const float* W_f2  = (const float*)d_in[17];
    const float* b_f2  = (const float*)d_in[18];
    const float* W_t1  = (const float*)d_in[19];
    const float* b_t1  = (const float*)d_in[20];
    const float* W_t2  = (const float*)d_in[21];
    const float* b_t2  = (const float*)d_in[22];
    const int*   Lrows = (const int*)d_in[23];
    const int*   Lcols = (const int*)d_in[24];
    float* out = (float*)d_out;

    float *p_x0T, *p_part;
    __nv_bfloat16 *p_x0Th, *p_xth, *p_Winh, *p_Wouth, *p_h2h;
    int *p_cnt, *p_off, *p_wp, *p_bsum;
    int2* p_cpack;
    cudaGetSymbolAddress((void**)&p_x0T,  g_x0T);
    cudaGetSymbolAddress((void**)&p_x0Th, g_x0Th);
    cudaGetSymbolAddress((void**)&p_xth,  g_xth);
    cudaGetSymbolAddress((void**)&p_Winh, g_Winh);
    cudaGetSymbolAddress((void**)&p_Wouth,g_Wouth);
    cudaGetSymbolAddress((void**)&p_part, g_part);
    cudaGetSymbolAddress((void**)&p_h2h,  g_h2h);
    cudaGetSymbolAddress((void**)&p_cnt,  g_cnt);
    cudaGetSymbolAddress((void**)&p_off,  g_off);
    cudaGetSymbolAddress((void**)&p_wp,   g_wp);
    cudaGetSymbolAddress((void**)&p_cpack,g_cpack);
    cudaGetSymbolAddress((void**)&p_bsum, g_bsum);

    // CSR build: hist -> scan1 (self-resets cnt) -> scan23 (zeroes loss) -> fill
    hist_kernel<<<(NNZV + 255) / 256, 256>>>(Lrows, p_cnt);
    scan1_kernel<<<64, 256>>>(p_cnt, p_off, p_bsum);
    scan23_kernel<<<1, 1024>>>(p_bsum, p_off, p_wp, out);
    fill_kernel<<<(NNZV + 255) / 256, 256>>>(Lrows, Lcols, Lvals, p_wp, p_cpack);

    // transpose + weight cvt (one launch)
    transcvt_kernel<<<12288, 256>>>(x0, p_x0T, p_x0Th, W_in, p_Winh, W_out, p_Wouth);

    // xt (bf16) = x0T - tc*Lx
    gather_kernel<<<NI, 128>>>(p_x0T, p_x0Th, p_off, p_cpack, t, p_xth);

    // GEMM1 partials (bf16 tensor cores), 32-way split-K for SM fill
    gemm1_bf16_kernel<<<dim3(2, 4, NSP1), 256>>>(p_xth, p_Winh, p_part, NI / NSP1);

    // entire middle section in one persistent kernel
    middle_kernel<<<NCTA_MID, 256>>>(t, W_t1, b_t1, W_t2, b_t2, b_in,
                                     W_qkv + 2 * DM * DM, b_qkv + 2 * DM,
                                     W_o, b_o, g1, be1, W_f1, b_f1,
                                     W_f2, b_f2, g2, be2);

    // loss = mean((h2 @ W_out^T + b_out - x0)^2)
    gemm_loss_bf16_kernel<<<dim3(2, NI / 128), 256>>>(p_h2h, p_Wouth, b_out, x0, out);
}